// round 2
// baseline (speedup 1.0000x reference)
#include <cuda_runtime.h>
#include <math.h>

// Problem constants
#define BATCH 1024
#define HID   1024
#define INSZ  55
#define SRC_STEPS 49   // SOURCE_SEQ_LEN - 1
#define TGT_STEPS 25

// Ping-pong hidden-state buffers (scratch via __device__ globals; no allocs allowed)
__device__ float g_h0[BATCH * HID];
__device__ float g_h1[BATCH * HID];

// ---------------------------------------------------------------------------
// Fused GRU step: h_out = GRUCell(x, h_in)
//   gi = x @ W_ih^T + b_ih ; gh = h @ W_hh^T + b_hh
//   r = sig(gi_r+gh_r); z = sig(gi_z+gh_z); n = tanh(gi_n + r*gh_n)
//   h' = (1-z)*n + z*h
// Tiling: BM=64 (batch) x BN=64 (hidden cols) per block, 3 gates fused.
// Grid (16,16), 256 threads, each thread owns 4x4 per gate (+4x4 gi_n).
// ---------------------------------------------------------------------------
__global__ __launch_bounds__(256, 1)
void gru_step_kernel(const float* __restrict__ x, int x_stride,
                     const float* __restrict__ h_in, float* __restrict__ h_out,
                     const float* __restrict__ Wih, const float* __restrict__ Whh,
                     const float* __restrict__ bih, const float* __restrict__ bhh)
{
    __shared__ float sA[16][64];        // [k][m]  (h / x tile, transposed)
    __shared__ float sB[3][16][64];     // [gate][k][n] (W tile, transposed)

    const int tid = threadIdx.x;
    const int tx  = tid & 15;           // 0..15  -> n sub-tile
    const int ty  = tid >> 4;           // 0..15  -> m sub-tile
    const int mBase = blockIdx.y * 64;
    const int nBase = blockIdx.x * 64;

    float acc[3][4][4];                 // gh_r, gh_z, gh_n (r/z also absorb gi)
    float accin[4][4];                  // gi_n (must stay separate: n = tanh(i_n + r*h_n))
#pragma unroll
    for (int g = 0; g < 3; g++)
#pragma unroll
        for (int i = 0; i < 4; i++)
#pragma unroll
            for (int j = 0; j < 4; j++) acc[g][i][j] = 0.f;
#pragma unroll
    for (int i = 0; i < 4; i++)
#pragma unroll
        for (int j = 0; j < 4; j++) accin[i][j] = 0.f;

    const int ldRow = tid >> 2;         // 0..63
    const int ldKq  = tid & 3;          // 0..3 (float4 chunk along k)

    // ---------------- Phase 1: gh = h_in @ W_hh^T  (K = HID) ----------------
    for (int k0 = 0; k0 < HID; k0 += 16) {
        __syncthreads();
        {
            float4 av = *(const float4*)&h_in[(mBase + ldRow) * HID + k0 + ldKq * 4];
            sA[ldKq * 4 + 0][ldRow] = av.x;
            sA[ldKq * 4 + 1][ldRow] = av.y;
            sA[ldKq * 4 + 2][ldRow] = av.z;
            sA[ldKq * 4 + 3][ldRow] = av.w;
#pragma unroll
            for (int g = 0; g < 3; g++) {
                int j = g * HID + nBase + ldRow;        // W_hh row
                float4 bv = *(const float4*)&Whh[j * HID + k0 + ldKq * 4];
                sB[g][ldKq * 4 + 0][ldRow] = bv.x;
                sB[g][ldKq * 4 + 1][ldRow] = bv.y;
                sB[g][ldKq * 4 + 2][ldRow] = bv.z;
                sB[g][ldKq * 4 + 3][ldRow] = bv.w;
            }
        }
        __syncthreads();
#pragma unroll
        for (int kk = 0; kk < 16; kk++) {
            float4 a  = *(const float4*)&sA[kk][ty * 4];
            float4 br = *(const float4*)&sB[0][kk][tx * 4];
            float4 bz = *(const float4*)&sB[1][kk][tx * 4];
            float4 bn = *(const float4*)&sB[2][kk][tx * 4];
            const float ar[4] = {a.x, a.y, a.z, a.w};
            const float vr[4] = {br.x, br.y, br.z, br.w};
            const float vz[4] = {bz.x, bz.y, bz.z, bz.w};
            const float vn[4] = {bn.x, bn.y, bn.z, bn.w};
#pragma unroll
            for (int i = 0; i < 4; i++)
#pragma unroll
                for (int j = 0; j < 4; j++) {
                    acc[0][i][j] += ar[i] * vr[j];
                    acc[1][i][j] += ar[i] * vz[j];
                    acc[2][i][j] += ar[i] * vn[j];
                }
        }
    }

    // ---------------- Phase 2: gi = x @ W_ih^T  (K = 55, padded) ------------
    for (int k0 = 0; k0 < INSZ; k0 += 16) {
        __syncthreads();
        {
#pragma unroll
            for (int q = 0; q < 4; q++) {
                int k = k0 + ldKq * 4 + q;
                float va = (k < INSZ) ? x[(mBase + ldRow) * x_stride + k] : 0.f;
                sA[ldKq * 4 + q][ldRow] = va;
#pragma unroll
                for (int g = 0; g < 3; g++) {
                    int j = g * HID + nBase + ldRow;
                    float vb = (k < INSZ) ? Wih[j * INSZ + k] : 0.f;
                    sB[g][ldKq * 4 + q][ldRow] = vb;
                }
            }
        }
        __syncthreads();
#pragma unroll
        for (int kk = 0; kk < 16; kk++) {
            float4 a  = *(const float4*)&sA[kk][ty * 4];
            float4 br = *(const float4*)&sB[0][kk][tx * 4];
            float4 bz = *(const float4*)&sB[1][kk][tx * 4];
            float4 bn = *(const float4*)&sB[2][kk][tx * 4];
            const float ar[4] = {a.x, a.y, a.z, a.w};
            const float vr[4] = {br.x, br.y, br.z, br.w};
            const float vz[4] = {bz.x, bz.y, bz.z, bz.w};
            const float vn[4] = {bn.x, bn.y, bn.z, bn.w};
#pragma unroll
            for (int i = 0; i < 4; i++)
#pragma unroll
                for (int j = 0; j < 4; j++) {
                    acc[0][i][j]  += ar[i] * vr[j];   // gi_r folds into gh_r
                    acc[1][i][j]  += ar[i] * vz[j];   // gi_z folds into gh_z
                    accin[i][j]   += ar[i] * vn[j];   // gi_n kept separate
                }
        }
    }

    // ---------------- Epilogue: gates + state update ------------------------
#pragma unroll
    for (int i = 0; i < 4; i++) {
        int m = mBase + ty * 4 + i;
#pragma unroll
        for (int j = 0; j < 4; j++) {
            int n = nBase + tx * 4 + j;
            float pr = acc[0][i][j] + bih[n]            + bhh[n];
            float pz = acc[1][i][j] + bih[HID + n]      + bhh[HID + n];
            float in_n = accin[i][j] + bih[2 * HID + n];
            float hn   = acc[2][i][j] + bhh[2 * HID + n];
            float r = 1.f / (1.f + expf(-pr));
            float z = 1.f / (1.f + expf(-pz));
            float nn = tanhf(in_n + r * hn);
            float hprev = h_in[m * HID + n];
            h_out[m * HID + n] = (1.f - z) * nn + z * hprev;
        }
    }
}

// ---------------------------------------------------------------------------
// Decoder output: out[b,i] = inp[b,i] + h[b,:] @ fc_w[i,:] + fc_b[i]
// One block per batch row; h row staged in smem; warp-per-output reduction.
// ---------------------------------------------------------------------------
__global__ __launch_bounds__(256)
void fc_out_kernel(const float* __restrict__ inp, int inp_stride,
                   const float* __restrict__ h,
                   const float* __restrict__ fcw, const float* __restrict__ fcb,
                   float* __restrict__ out, int out_stride)
{
    const int b = blockIdx.x;
    __shared__ float sh[HID];
    for (int i = threadIdx.x; i < HID; i += 256) sh[i] = h[b * HID + i];
    __syncthreads();

    const int warp = threadIdx.x >> 5;
    const int lane = threadIdx.x & 31;
    for (int i = warp; i < INSZ; i += 8) {
        float s = 0.f;
#pragma unroll 8
        for (int k = lane; k < HID; k += 32) s += sh[k] * fcw[i * HID + k];
#pragma unroll
        for (int o = 16; o; o >>= 1) s += __shfl_xor_sync(0xffffffffu, s, o);
        if (lane == 0)
            out[b * out_stride + i] = inp[b * inp_stride + i] + s + fcb[i];
    }
}

__global__ void zero_kernel(float* p, int n)
{
    int i = blockIdx.x * blockDim.x + threadIdx.x;
    if (i < n) p[i] = 0.f;
}

extern "C" void kernel_launch(void* const* d_in, const int* in_sizes, int n_in,
                              void* d_out, int out_size)
{
    const float* enc = (const float*)d_in[0];   // [1024, 50, 55]
    const float* dec = (const float*)d_in[1];   // [1024, 25, 55]
    const float* Wih = (const float*)d_in[2];   // [3072, 55]
    const float* Whh = (const float*)d_in[3];   // [3072, 1024]
    const float* bih = (const float*)d_in[4];   // [3072]
    const float* bhh = (const float*)d_in[5];   // [3072]
    const float* fcw = (const float*)d_in[6];   // [55, 1024]
    const float* fcb = (const float*)d_in[7];   // [55]
    float* out = (float*)d_out;                 // [1024, 25, 55]

    float *h0, *h1;
    cudaGetSymbolAddress((void**)&h0, g_h0);
    cudaGetSymbolAddress((void**)&h1, g_h1);
    float* bufs[2] = {h0, h1};

    zero_kernel<<<(BATCH * HID + 255) / 256, 256>>>(h0, BATCH * HID);

    dim3 grid(HID / 64, BATCH / 64);   // (16,16)
    int cur = 0;

    // Encoder: 49 steps over encoder_inputs[:, t, :]
    for (int t = 0; t < SRC_STEPS; t++) {
        gru_step_kernel<<<grid, 256>>>(enc + t * INSZ, 50 * INSZ,
                                       bufs[cur], bufs[cur ^ 1],
                                       Wih, Whh, bih, bhh);
        cur ^= 1;
    }

    // Decoder: autoregressive; input t=0 is decoder_inputs[:,0,:], then prev out
    for (int t = 0; t < TGT_STEPS; t++) {
        const float* xp = (t == 0) ? dec : (out + (t - 1) * INSZ);
        gru_step_kernel<<<grid, 256>>>(xp, TGT_STEPS * INSZ,
                                       bufs[cur], bufs[cur ^ 1],
                                       Wih, Whh, bih, bhh);
        cur ^= 1;
        fc_out_kernel<<<BATCH, 256>>>(xp, TGT_STEPS * INSZ,
                                      bufs[cur], fcw, fcb,
                                      out + t * INSZ, TGT_STEPS * INSZ);
    }
}

// round 5
// speedup vs baseline: 1.4749x; 1.4749x over previous
#include <cuda_runtime.h>
#include <cuda_bf16.h>
#include <cstdint>
#include <math.h>

#define BATCH 1024
#define HID   1024
#define NGATE 3072
#define INSZ  55
#define KPAD  64
#define SRC_STEPS 49
#define TGT_STEPS 25
#define OUT_STRIDE (TGT_STEPS * INSZ)   // 1375

// ---------------- device scratch (no allocs allowed) ----------------
__device__ __align__(16) float g_h0[BATCH * HID];
__device__ __align__(16) float g_h1[BATCH * HID];
__device__ __align__(16) __nv_bfloat16 g_h0h[BATCH * HID];
__device__ __align__(16) __nv_bfloat16 g_h0l[BATCH * HID];
__device__ __align__(16) __nv_bfloat16 g_h1h[BATCH * HID];
__device__ __align__(16) __nv_bfloat16 g_h1l[BATCH * HID];
__device__ __align__(16) __nv_bfloat16 g_whh_h[NGATE * HID];
__device__ __align__(16) __nv_bfloat16 g_whh_l[NGATE * HID];
__device__ __align__(16) __nv_bfloat16 g_wih_h[NGATE * KPAD];
__device__ __align__(16) __nv_bfloat16 g_wih_l[NGATE * KPAD];
__device__ __align__(16) __nv_bfloat16 g_encx_h[SRC_STEPS * BATCH * KPAD];
__device__ __align__(16) __nv_bfloat16 g_encx_l[SRC_STEPS * BATCH * KPAD];
__device__ __align__(16) __nv_bfloat16 g_decx_h[TGT_STEPS * BATCH * KPAD];
__device__ __align__(16) __nv_bfloat16 g_decx_l[TGT_STEPS * BATCH * KPAD];

// ---------------- PTX helpers (sm_80-compatible: mma.sync / ldmatrix / cp.async) --
__device__ __forceinline__ uint32_t smem_u32(const void* p) {
    uint32_t a;
    asm("{ .reg .u64 t; cvta.to.shared.u64 t, %1; cvt.u32.u64 %0, t; }" : "=r"(a) : "l"(p));
    return a;
}
__device__ __forceinline__ void cp16(uint32_t dst, const void* src) {
    asm volatile("cp.async.cg.shared.global [%0], [%1], 16;"
                 :: "r"(dst), "l"(__cvta_generic_to_global(src)) : "memory");
}
#define CP_COMMIT() asm volatile("cp.async.commit_group;" ::: "memory")
#define CP_WAIT(n)  asm volatile("cp.async.wait_group %0;" :: "n"(n) : "memory")

__device__ __forceinline__ void ldsm4(uint32_t* r, uint32_t addr) {
    asm volatile("ldmatrix.sync.aligned.m8n8.x4.shared.b16 {%0,%1,%2,%3}, [%4];"
        : "=r"(r[0]), "=r"(r[1]), "=r"(r[2]), "=r"(r[3]) : "r"(addr));
}
__device__ __forceinline__ void mma16816(float* c, const uint32_t* a, uint32_t b0, uint32_t b1) {
    asm volatile("mma.sync.aligned.m16n8k16.row.col.f32.bf16.bf16.f32 "
        "{%0,%1,%2,%3}, {%4,%5,%6,%7}, {%8,%9}, {%0,%1,%2,%3};"
        : "+f"(c[0]), "+f"(c[1]), "+f"(c[2]), "+f"(c[3])
        : "r"(a[0]), "r"(a[1]), "r"(a[2]), "r"(a[3]), "r"(b0), "r"(b1));
}

// ---------------- GRU step kernel: bf16 hi/lo compensated mma.sync ----------
// CTA: 64 batch rows x 64 hidden cols x 4 gate regions (r, z, h_n, i_n).
// 8 warps: warpM = wid&1 (32 rows each), warpN = wid>>1 = gate region.
// K pipeline: 32 main iters (K=1024, Whh) + 2 tail iters (K=64, Wih).
//   main: regions r,z,h_n active (B slots 0,1,2 <- Whh gates 0,1,2)
//   tail: regions r,z,i_n active (B slots 0,1,2 <- Wih gates 0,1,2)
#define BK 32
#define ROWB 80                 // 32 halves padded to 40 -> 80 bytes
#define A_TILE 5120             // 64 rows * 80B
#define B_SLOT 5120
#define STAGE_BYTES 40960       // Ah,Al (10240) + Bh[3] (15360) + Bl[3] (15360)
#define SMEM_BYTES  81920
#define NITER_MAIN 32
#define NITER_TOT  34
#define EPW 66                  // epilogue smem row stride (floats)

struct StageSrc {
    const __nv_bfloat16* a[2];
    const __nv_bfloat16* b[2];
    int astr, bstr, k0;
};

__global__ __launch_bounds__(256, 1)
void gru_mma_kernel(const __nv_bfloat16* __restrict__ ah, const __nv_bfloat16* __restrict__ al,
                    const __nv_bfloat16* __restrict__ xh, const __nv_bfloat16* __restrict__ xl,
                    const float* __restrict__ bih, const float* __restrict__ bhh,
                    const float* __restrict__ h_in, float* __restrict__ h_out,
                    __nv_bfloat16* __restrict__ hoh, __nv_bfloat16* __restrict__ hol)
{
    extern __shared__ char smem[];
    const uint32_t sb = smem_u32(smem);
    const int tid = threadIdx.x;
    const int lane = tid & 31, wid = tid >> 5;
    const int warpM = wid & 1, warpN = wid >> 1;
    const int mBase = blockIdx.y * 64, nBase = blockIdx.x * 64;

    float acc[2][8][4];
#pragma unroll
    for (int a0 = 0; a0 < 2; a0++)
#pragma unroll
        for (int b0 = 0; b0 < 8; b0++)
#pragma unroll
            for (int c0 = 0; c0 < 4; c0++) acc[a0][b0][c0] = 0.f;

    // ---- stage loader ----
    auto load_stage = [&](int it) {
        const int s = it & 1;
        const uint32_t st = sb + s * STAGE_BYTES;
        StageSrc src;
        if (it < NITER_MAIN) {
            src.a[0] = ah; src.a[1] = al; src.astr = HID;
            src.b[0] = g_whh_h; src.b[1] = g_whh_l; src.bstr = HID;
            src.k0 = it * BK;
        } else {
            src.a[0] = xh; src.a[1] = xl; src.astr = KPAD;
            src.b[0] = g_wih_h; src.b[1] = g_wih_l; src.bstr = KPAD;
            src.k0 = (it - NITER_MAIN) * BK;
        }
        // A: 2(hi/lo) * 64 rows * 4 chunks = 512
#pragma unroll
        for (int i = tid; i < 512; i += 256) {
            int hl = i >> 8, rem = i & 255, row = rem >> 2, c = rem & 3;
            const __nv_bfloat16* p = src.a[hl] + (long)(mBase + row) * src.astr + src.k0 + c * 8;
            cp16(st + hl * A_TILE + row * ROWB + c * 16, p);
        }
        // B: 3 slots * 2(hi/lo) * 64 rows * 4 chunks = 1536
#pragma unroll
        for (int i = tid; i < 1536; i += 256) {
            int slot = i / 512, rem = i % 512, hl = rem >> 8, r2 = rem & 255;
            int row = r2 >> 2, c = r2 & 3;
            const __nv_bfloat16* p = src.b[hl] +
                (long)(slot * HID + nBase + row) * src.bstr + src.k0 + c * 8;
            cp16(st + 10240 + hl * 15360 + slot * B_SLOT + row * ROWB + c * 16, p);
        }
        CP_COMMIT();
    };

    // ---- compute one stage ----
    auto compute = [&](int it) {
        const int s = it & 1;
        const uint32_t st = sb + s * STAGE_BYTES;
        const bool tail = (it >= NITER_MAIN);
        const bool active = tail ? (warpN != 2) : (warpN != 3);
        if (!active) return;
        const int slot = (warpN == 3) ? 2 : warpN;
        const uint32_t bh_base = st + 10240 + slot * B_SLOT;
        const uint32_t bl_base = bh_base + 15360;
        const int arow = warpM * 32 + (lane & 15);
        const int acolh = ((lane >> 4) << 3);            // 0 or 8 halves
        const int bn = (lane & 7) + ((lane >> 4) << 3);  // 0..15
        const int bkh = ((lane >> 3) & 1) << 3;          // 0 or 8 halves
#pragma unroll
        for (int kb = 0; kb < 2; kb++) {
            uint32_t Ah[2][4], Al[2][4];
#pragma unroll
            for (int mf = 0; mf < 2; mf++) {
                uint32_t ao = st + (arow + mf * 16) * ROWB + (acolh + kb * 16) * 2;
                ldsm4(Ah[mf], ao);
                ldsm4(Al[mf], ao + A_TILE);
            }
            const uint32_t bofs = bn * ROWB + (bkh + kb * 16) * 2;
            uint32_t B[4][4];
            // pass 1+2: Bh with Ah and Al
#pragma unroll
            for (int g = 0; g < 4; g++) ldsm4(B[g], bh_base + g * 1280 + bofs);
#pragma unroll
            for (int mf = 0; mf < 2; mf++)
#pragma unroll
                for (int nf = 0; nf < 8; nf++)
                    mma16816(acc[mf][nf], Ah[mf], B[nf >> 1][(nf & 1) * 2], B[nf >> 1][(nf & 1) * 2 + 1]);
#pragma unroll
            for (int mf = 0; mf < 2; mf++)
#pragma unroll
                for (int nf = 0; nf < 8; nf++)
                    mma16816(acc[mf][nf], Al[mf], B[nf >> 1][(nf & 1) * 2], B[nf >> 1][(nf & 1) * 2 + 1]);
            // pass 3: Bl with Ah
#pragma unroll
            for (int g = 0; g < 4; g++) ldsm4(B[g], bl_base + g * 1280 + bofs);
#pragma unroll
            for (int mf = 0; mf < 2; mf++)
#pragma unroll
                for (int nf = 0; nf < 8; nf++)
                    mma16816(acc[mf][nf], Ah[mf], B[nf >> 1][(nf & 1) * 2], B[nf >> 1][(nf & 1) * 2 + 1]);
        }
    };

    // ---- pipelined main + tail loop ----
    load_stage(0);
    for (int it = 0; it < NITER_TOT; it++) {
        if (it + 1 < NITER_TOT) {
            load_stage(it + 1);
            CP_WAIT(1);
        } else {
            CP_WAIT(0);
        }
        __syncthreads();
        compute(it);
        __syncthreads();
    }

    // ---- epilogue: accums -> smem (region-major), combine, write ----
    float* ep = (float*)smem;   // [4 regions][64 m][stride EPW]
#pragma unroll
    for (int mf = 0; mf < 2; mf++)
#pragma unroll
        for (int nf = 0; nf < 8; nf++) {
            int r0 = warpM * 32 + mf * 16 + (lane >> 2);
            int c0 = nf * 8 + (lane & 3) * 2;
            float2 v01 = make_float2(acc[mf][nf][0], acc[mf][nf][1]);
            float2 v23 = make_float2(acc[mf][nf][2], acc[mf][nf][3]);
            *(float2*)&ep[(warpN * 64 + r0) * EPW + c0] = v01;
            *(float2*)&ep[(warpN * 64 + r0 + 8) * EPW + c0] = v23;
        }
    __syncthreads();

    for (int i = tid; i < 4096; i += 256) {
        int m = i >> 6, j = i & 63;
        int n = nBase + j;
        long gm = mBase + m;
        float pr = ep[(0 * 64 + m) * EPW + j] + bih[n] + bhh[n];
        float pz = ep[(1 * 64 + m) * EPW + j] + bih[HID + n] + bhh[HID + n];
        float ph = ep[(2 * 64 + m) * EPW + j] + bhh[2 * HID + n];
        float pi = ep[(3 * 64 + m) * EPW + j] + bih[2 * HID + n];
        float r = 1.f / (1.f + expf(-pr));
        float z = 1.f / (1.f + expf(-pz));
        float nn = tanhf(pi + r * ph);
        float hprev = h_in[gm * HID + n];
        float ho = (1.f - z) * nn + z * hprev;
        h_out[gm * HID + n] = ho;
        __nv_bfloat16 hi = __float2bfloat16(ho);
        hoh[gm * HID + n] = hi;
        hol[gm * HID + n] = __float2bfloat16(ho - __bfloat162float(hi));
    }
}

// ---------------------------------------------------------------------------
// Decoder FC: out[b,o] = x[b,o] + h[b,:]@fcw[o,:] + fcb[o]; also emits bf16
// hi/lo split of out (padded to 64) as the next GRU step's input.
// ---------------------------------------------------------------------------
__global__ __launch_bounds__(256)
void fc_kernel(const float* __restrict__ x, const float* __restrict__ h,
               const float* __restrict__ fcw, const float* __restrict__ fcb,
               float* __restrict__ out_t,
               __nv_bfloat16* __restrict__ nxh, __nv_bfloat16* __restrict__ nxl)
{
    const int wid = threadIdx.x >> 5, lane = threadIdx.x & 31;
    const int b = blockIdx.x * 8 + wid;
    float hreg[32];
#pragma unroll
    for (int i = 0; i < 32; i++) hreg[i] = h[(long)b * HID + lane + 32 * i];

    for (int o = 0; o < INSZ; o++) {
        float s = 0.f;
#pragma unroll
        for (int i = 0; i < 32; i++) s += hreg[i] * fcw[(long)o * HID + lane + 32 * i];
#pragma unroll
        for (int off = 16; off; off >>= 1) s += __shfl_xor_sync(0xffffffffu, s, off);
        if (lane == 0) {
            float v = x[(long)b * OUT_STRIDE + o] + s + fcb[o];
            out_t[(long)b * OUT_STRIDE + o] = v;
            if (nxh) {
                __nv_bfloat16 hi = __float2bfloat16(v);
                nxh[(long)b * KPAD + o] = hi;
                nxl[(long)b * KPAD + o] = __float2bfloat16(v - __bfloat162float(hi));
            }
        }
    }
    if (nxh && lane < KPAD - INSZ) {
        nxh[(long)b * KPAD + INSZ + lane] = __float2bfloat16(0.f);
        nxl[(long)b * KPAD + INSZ + lane] = __float2bfloat16(0.f);
    }
}

// ---------------- prep kernels ----------------
__global__ void split_whh_kernel(const float* __restrict__ W) {
    long i = blockIdx.x * 256 + threadIdx.x;
    if (i >= (long)NGATE * HID) return;
    float v = W[i];
    __nv_bfloat16 hi = __float2bfloat16(v);
    g_whh_h[i] = hi;
    g_whh_l[i] = __float2bfloat16(v - __bfloat162float(hi));
}
__global__ void split_wih_kernel(const float* __restrict__ W) {
    long i = blockIdx.x * 256 + threadIdx.x;
    if (i >= (long)NGATE * KPAD) return;
    int row = (int)(i >> 6), k = (int)(i & 63);
    float v = (k < INSZ) ? W[(long)row * INSZ + k] : 0.f;
    __nv_bfloat16 hi = __float2bfloat16(v);
    g_wih_h[i] = hi;
    g_wih_l[i] = __float2bfloat16(v - __bfloat162float(hi));
}
__global__ void split_encx_kernel(const float* __restrict__ enc) {
    long i = blockIdx.x * 256 + threadIdx.x;
    if (i >= (long)SRC_STEPS * BATCH * KPAD) return;
    int t = (int)(i / (BATCH * KPAD));
    int r = (int)(i % (BATCH * KPAD));
    int b = r >> 6, k = r & 63;
    float v = (k < INSZ) ? enc[((long)b * 50 + t) * INSZ + k] : 0.f;
    __nv_bfloat16 hi = __float2bfloat16(v);
    g_encx_h[i] = hi;
    g_encx_l[i] = __float2bfloat16(v - __bfloat162float(hi));
}
__global__ void split_decx0_kernel(const float* __restrict__ dec) {
    long i = blockIdx.x * 256 + threadIdx.x;
    if (i >= (long)BATCH * KPAD) return;
    int b = (int)(i >> 6), k = (int)(i & 63);
    float v = (k < INSZ) ? dec[(long)b * OUT_STRIDE + k] : 0.f;
    __nv_bfloat16 hi = __float2bfloat16(v);
    g_decx_h[i] = hi;
    g_decx_l[i] = __float2bfloat16(v - __bfloat162float(hi));
}
__global__ void zero_state_kernel() {
    long i = blockIdx.x * 256 + threadIdx.x;
    if (i >= (long)BATCH * HID) return;
    g_h0[i] = 0.f;
    g_h0h[i] = __float2bfloat16(0.f);
    g_h0l[i] = __float2bfloat16(0.f);
}

extern "C" void kernel_launch(void* const* d_in, const int* in_sizes, int n_in,
                              void* d_out, int out_size)
{
    const float* enc = (const float*)d_in[0];
    const float* dec = (const float*)d_in[1];
    const float* Wih = (const float*)d_in[2];
    const float* Whh = (const float*)d_in[3];
    const float* bih = (const float*)d_in[4];
    const float* bhh = (const float*)d_in[5];
    const float* fcw = (const float*)d_in[6];
    const float* fcb = (const float*)d_in[7];
    float* out = (float*)d_out;

    cudaFuncSetAttribute(gru_mma_kernel, cudaFuncAttributeMaxDynamicSharedMemorySize, SMEM_BYTES);

    float *h0, *h1;
    __nv_bfloat16 *h0h, *h0l, *h1h, *h1l, *encxh, *encxl, *decxh, *decxl;
    cudaGetSymbolAddress((void**)&h0, g_h0);
    cudaGetSymbolAddress((void**)&h1, g_h1);
    cudaGetSymbolAddress((void**)&h0h, g_h0h);
    cudaGetSymbolAddress((void**)&h0l, g_h0l);
    cudaGetSymbolAddress((void**)&h1h, g_h1h);
    cudaGetSymbolAddress((void**)&h1l, g_h1l);
    cudaGetSymbolAddress((void**)&encxh, g_encx_h);
    cudaGetSymbolAddress((void**)&encxl, g_encx_l);
    cudaGetSymbolAddress((void**)&decxh, g_decx_h);
    cudaGetSymbolAddress((void**)&decxl, g_decx_l);

    split_whh_kernel<<<(NGATE * HID + 255) / 256, 256>>>(Whh);
    split_wih_kernel<<<(NGATE * KPAD + 255) / 256, 256>>>(Wih);
    split_encx_kernel<<<(SRC_STEPS * BATCH * KPAD + 255) / 256, 256>>>(enc);
    split_decx0_kernel<<<(BATCH * KPAD + 255) / 256, 256>>>(dec);
    zero_state_kernel<<<(BATCH * HID + 255) / 256, 256>>>();

    float* hf[2] = {h0, h1};
    __nv_bfloat16* hsh[2] = {h0h, h1h};
    __nv_bfloat16* hsl[2] = {h0l, h1l};
    int cur = 0;
    dim3 grid(16, 16);   // x: n-tiles (hidden/64), y: m-tiles (batch/64)

    for (int t = 0; t < SRC_STEPS; t++) {
        gru_mma_kernel<<<grid, 256, SMEM_BYTES>>>(
            hsh[cur], hsl[cur],
            encxh + (long)t * BATCH * KPAD, encxl + (long)t * BATCH * KPAD,
            bih, bhh, hf[cur], hf[cur ^ 1], hsh[cur ^ 1], hsl[cur ^ 1]);
        cur ^= 1;
    }

    for (int t = 0; t < TGT_STEPS; t++) {
        gru_mma_kernel<<<grid, 256, SMEM_BYTES>>>(
            hsh[cur], hsl[cur],
            decxh + (long)t * BATCH * KPAD, decxl + (long)t * BATCH * KPAD,
            bih, bhh, hf[cur], hf[cur ^ 1], hsh[cur ^ 1], hsl[cur ^ 1]);
        cur ^= 1;
        const float* xp = (t == 0) ? dec : (out + (long)(t - 1) * INSZ);
        bool last = (t == TGT_STEPS - 1);
        fc_kernel<<<128, 256>>>(xp, hf[cur], fcw, fcb, out + (long)t * INSZ,
                                last ? (__nv_bfloat16*)nullptr : decxh + (long)(t + 1) * BATCH * KPAD,
                                last ? (__nv_bfloat16*)nullptr : decxl + (long)(t + 1) * BATCH * KPAD);
    }
}

// round 6
// speedup vs baseline: 2.1232x; 1.4395x over previous
#include <cuda_runtime.h>
#include <cuda_bf16.h>
#include <cstdint>
#include <math.h>

#define BATCH 1024
#define HID   1024
#define NGATE 3072
#define INSZ  55
#define KPAD  64
#define SRC_STEPS 49
#define TGT_STEPS 25
#define TOT_STEPS 74
#define OUT_STRIDE (TGT_STEPS * INSZ)   // 1375
#define NCTA 128

// ---------------- device scratch (no allocs allowed) ----------------
__device__ __align__(16) float g_h0[BATCH * HID];
__device__ __align__(16) float g_h1[BATCH * HID];
__device__ __align__(16) __nv_bfloat16 g_h0h[BATCH * HID];
__device__ __align__(16) __nv_bfloat16 g_h0l[BATCH * HID];
__device__ __align__(16) __nv_bfloat16 g_h1h[BATCH * HID];
__device__ __align__(16) __nv_bfloat16 g_h1l[BATCH * HID];
__device__ __align__(16) __nv_bfloat16 g_whh_h[NGATE * HID];
__device__ __align__(16) __nv_bfloat16 g_whh_l[NGATE * HID];
__device__ __align__(16) __nv_bfloat16 g_wih_h[NGATE * KPAD];
__device__ __align__(16) __nv_bfloat16 g_wih_l[NGATE * KPAD];
__device__ __align__(16) __nv_bfloat16 g_encx_h[SRC_STEPS * BATCH * KPAD];
__device__ __align__(16) __nv_bfloat16 g_encx_l[SRC_STEPS * BATCH * KPAD];
__device__ __align__(16) __nv_bfloat16 g_decx_h[TGT_STEPS * BATCH * KPAD];
__device__ __align__(16) __nv_bfloat16 g_decx_l[TGT_STEPS * BATCH * KPAD];
__device__ __align__(16) float g_gin[BATCH * HID];   // i_n = x@Wih_n partials
__device__ int g_bar_ctr;

// ---------------- PTX helpers (sm_80-class; valid on base sm_103) ----------
__device__ __forceinline__ uint32_t smem_u32(const void* p) {
    uint32_t a;
    asm("{ .reg .u64 t; cvta.to.shared.u64 t, %1; cvt.u32.u64 %0, t; }" : "=r"(a) : "l"(p));
    return a;
}
__device__ __forceinline__ void cp16(uint32_t dst, const void* src) {
    asm volatile("cp.async.cg.shared.global [%0], [%1], 16;"
                 :: "r"(dst), "l"(__cvta_generic_to_global(src)) : "memory");
}
#define CP_COMMIT() asm volatile("cp.async.commit_group;" ::: "memory")
#define CP_WAIT(n)  asm volatile("cp.async.wait_group %0;" :: "n"(n) : "memory")

__device__ __forceinline__ void ldsm4(uint32_t* r, uint32_t addr) {
    asm volatile("ldmatrix.sync.aligned.m8n8.x4.shared.b16 {%0,%1,%2,%3}, [%4];"
        : "=r"(r[0]), "=r"(r[1]), "=r"(r[2]), "=r"(r[3]) : "r"(addr));
}
__device__ __forceinline__ void mma16816(float* c, const uint32_t* a, uint32_t b0, uint32_t b1) {
    asm volatile("mma.sync.aligned.m16n8k16.row.col.f32.bf16.bf16.f32 "
        "{%0,%1,%2,%3}, {%4,%5,%6,%7}, {%8,%9}, {%0,%1,%2,%3};"
        : "+f"(c[0]), "+f"(c[1]), "+f"(c[2]), "+f"(c[3])
        : "r"(a[0]), "r"(a[1]), "r"(a[2]), "r"(a[3]), "r"(b0), "r"(b1));
}

// ---------------- geometry ----------------
// CTA: 128 batch rows x 64 hidden cols (= 192 gate-cols). 512 thr, 16 warps.
// warpM = wid&7 (16 rows each), warpN = wid>>3 (96 gate-cols each). All active.
// Stage: K=32. smem per stage: A(hi/lo) 2*128*80 + B(hi/lo) 2*192*80 = 51200B.
// 2 stages + epilogue region (128 x 200 fp32).
#define ROWB 80
#define OFF_B 20480
#define STAGE 51200
#define NSTAGES 34              // 2 Wih (K=64) first, then 32 Whh (K=1024)
#define EPW 200
#define EP_OFF 102400
#define SMEM_BYTES (EP_OFF + 128 * EPW * 4)   // 204800

__device__ __forceinline__ void grid_bar(int target) {
    __syncthreads();
    if (threadIdx.x == 0) {
        __threadfence();
        atomicAdd(&g_bar_ctr, 1);
        while (*(volatile int*)&g_bar_ctr < target) __nanosleep(64);
    }
    __syncthreads();
}

// ---------------------------------------------------------------------------
// Persistent kernel: all 74 GRU steps + 25 decoder FC steps, one launch.
// ---------------------------------------------------------------------------
__global__ __launch_bounds__(512, 1)
void seq2seq_persistent(const float* __restrict__ dec,
                        const float* __restrict__ bih, const float* __restrict__ bhh,
                        const float* __restrict__ fcw, const float* __restrict__ fcb,
                        float* __restrict__ out)
{
    extern __shared__ char smem[];
    const uint32_t sb = smem_u32(smem);
    const int tid = threadIdx.x;
    const int lane = tid & 31, wid = tid >> 5;
    const int warpM = wid & 7, warpN = wid >> 3;
    const int nT = blockIdx.x & 15, mT = blockIdx.x >> 4;
    const int mBase = mT * 128, nBase = nT * 64;

    float* hf[2] = {g_h0, g_h1};
    __nv_bfloat16* hsh[2] = {g_h0h, g_h1h};
    __nv_bfloat16* hsl[2] = {g_h0l, g_h1l};

    // precomputed ldsm lane addressing (within stage buffer)
    const int arow = warpM * 16 + (lane & 15);
    const int acolh = (lane >> 4) << 3;
    const int bn = (lane & 7) + ((lane >> 4) << 3);
    const int bkh = ((lane >> 3) & 1) << 3;
    const uint32_t a_lofs = arow * ROWB + acolh * 2;
    const uint32_t b_lofs = (warpN * 96 + bn) * ROWB + bkh * 2;

    int cur = 0, nbar = 0;

    for (int t = 0; t < TOT_STEPS; t++) {
        const __nv_bfloat16 *ah = hsh[cur], *al = hsl[cur];
        const __nv_bfloat16 *xh, *xl;
        if (t < SRC_STEPS) {
            xh = g_encx_h + (long)t * BATCH * KPAD;
            xl = g_encx_l + (long)t * BATCH * KPAD;
        } else {
            xh = g_decx_h + (long)(t - SRC_STEPS) * BATCH * KPAD;
            xl = g_decx_l + (long)(t - SRC_STEPS) * BATCH * KPAD;
        }

        float acc[12][4];
#pragma unroll
        for (int i = 0; i < 12; i++)
#pragma unroll
            for (int j = 0; j < 4; j++) acc[i][j] = 0.f;

        // ---- stage loader: it<2 -> Wih/x (k0=it*32); else Whh/h (k0=(it-2)*32)
        auto load_stage = [&](int it) {
            const uint32_t st = sb + (uint32_t)(it & 1) * STAGE;
            const __nv_bfloat16 *As[2], *Bs[2];
            int astr, bstr, k0;
            if (it < 2) {
                As[0] = xh; As[1] = xl; astr = KPAD;
                Bs[0] = g_wih_h; Bs[1] = g_wih_l; bstr = KPAD;
                k0 = it * 32;
            } else {
                As[0] = ah; As[1] = al; astr = HID;
                Bs[0] = g_whh_h; Bs[1] = g_whh_l; bstr = HID;
                k0 = (it - 2) * 32;
            }
            // A: 2 * 128 rows * 4 chunks = 1024 cp16
#pragma unroll
            for (int i = tid; i < 1024; i += 512) {
                int hl = i >> 9, rem = i & 511, row = rem >> 2, c = rem & 3;
                cp16(st + hl * 10240 + row * ROWB + c * 16,
                     As[hl] + (long)(mBase + row) * astr + k0 + c * 8);
            }
            // B: 2 * 192 rows * 4 chunks = 1536 cp16
#pragma unroll
            for (int i = tid; i < 1536; i += 512) {
                int hl = i / 768, rem = i % 768, grow = rem >> 2, c = rem & 3;
                long wrow = (long)((grow >> 6) * HID + nBase + (grow & 63));
                cp16(st + OFF_B + hl * 15360 + grow * ROWB + c * 16,
                     Bs[hl] + wrow * bstr + k0 + c * 8);
            }
            CP_COMMIT();
        };

        load_stage(0);
        for (int it = 0; it < NSTAGES; it++) {
            if (it + 1 < NSTAGES) { load_stage(it + 1); CP_WAIT(1); }
            else                  { CP_WAIT(0); }
            __syncthreads();

            // ---- compute stage ----
            {
                const uint32_t st = sb + (uint32_t)(it & 1) * STAGE;
                const uint32_t Bh_b = st + OFF_B, Bl_b = st + OFF_B + 15360;
#pragma unroll
                for (int kb = 0; kb < 2; kb++) {
                    uint32_t Ahf[4], Alf[4];
                    uint32_t ao = st + a_lofs + kb * 32;  // kb*16 halves = 32B
                    ldsm4(Ahf, ao);
                    ldsm4(Alf, ao + 10240);
                    const uint32_t bo = b_lofs + kb * 32;
                    uint32_t Bf[6][4];
#pragma unroll
                    for (int g = 0; g < 6; g++) ldsm4(Bf[g], Bh_b + bo + g * (16 * ROWB));
#pragma unroll
                    for (int g = 0; g < 6; g++) {
                        mma16816(acc[g * 2],     Ahf, Bf[g][0], Bf[g][1]);
                        mma16816(acc[g * 2 + 1], Ahf, Bf[g][2], Bf[g][3]);
                    }
#pragma unroll
                    for (int g = 0; g < 6; g++) {
                        mma16816(acc[g * 2],     Alf, Bf[g][0], Bf[g][1]);
                        mma16816(acc[g * 2 + 1], Alf, Bf[g][2], Bf[g][3]);
                    }
#pragma unroll
                    for (int g = 0; g < 6; g++) {
                        uint32_t Blf[4];
                        ldsm4(Blf, Bl_b + bo + g * (16 * ROWB));
                        mma16816(acc[g * 2],     Ahf, Blf[0], Blf[1]);
                        mma16816(acc[g * 2 + 1], Ahf, Blf[2], Blf[3]);
                    }
                }
            }

            // after the 2 Wih stages: stash i_n (gate-cols 128..191) and reuse regs
            if (it == 1 && warpN == 1) {
                const int r0 = warpM * 16 + (lane >> 2);
#pragma unroll
                for (int nf = 4; nf < 12; nf++) {
                    int j = nBase + nf * 8 - 32 + (lane & 3) * 2;
                    *(float2*)&g_gin[(long)(mBase + r0) * HID + j] =
                        make_float2(acc[nf][0], acc[nf][1]);
                    *(float2*)&g_gin[(long)(mBase + r0 + 8) * HID + j] =
                        make_float2(acc[nf][2], acc[nf][3]);
                    acc[nf][0] = acc[nf][1] = acc[nf][2] = acc[nf][3] = 0.f;
                }
            }
            __syncthreads();
        }

        // ---- epilogue: frags -> ep smem, gates, h update ----
        float* ep = (float*)(smem + EP_OFF);
        {
            const int r0 = warpM * 16 + (lane >> 2);
#pragma unroll
            for (int nf = 0; nf < 12; nf++) {
                int c = warpN * 96 + nf * 8 + (lane & 3) * 2;
                *(float2*)&ep[r0 * EPW + c]       = make_float2(acc[nf][0], acc[nf][1]);
                *(float2*)&ep[(r0 + 8) * EPW + c] = make_float2(acc[nf][2], acc[nf][3]);
            }
        }
        __syncthreads();

        {
            const float* h_in = hf[cur];
            float* h_out = hf[cur ^ 1];
            __nv_bfloat16* hoh = hsh[cur ^ 1];
            __nv_bfloat16* hol = hsl[cur ^ 1];
            for (int i = tid; i < 8192; i += 512) {
                int m = i >> 6, j = i & 63;
                int n = nBase + j;
                long gm = mBase + m;
                float pr = ep[m * EPW + j]        + bih[n] + bhh[n];
                float pz = ep[m * EPW + 64 + j]   + bih[HID + n] + bhh[HID + n];
                float ph = ep[m * EPW + 128 + j]  + bhh[2 * HID + n];
                float pi = g_gin[gm * HID + n]    + bih[2 * HID + n];
                float r = 1.f / (1.f + expf(-pr));
                float z = 1.f / (1.f + expf(-pz));
                float nn = tanhf(pi + r * ph);
                float hprev = __ldcg(&h_in[gm * HID + n]);
                float ho = (1.f - z) * nn + z * hprev;
                h_out[gm * HID + n] = ho;
                __nv_bfloat16 hi = __float2bfloat16(ho);
                hoh[gm * HID + n] = hi;
                hol[gm * HID + n] = __float2bfloat16(ho - __bfloat162float(hi));
            }
        }
        cur ^= 1;
        grid_bar(++nbar * NCTA);

        // ---- decoder FC ----
        if (t >= SRC_STEPS) {
            const int td = t - SRC_STEPS;
            const float* hcur = hf[cur];
            const int b = blockIdx.x * 8 + (wid >> 1);
            const int half = wid & 1;
            float hreg[32];
#pragma unroll
            for (int i = 0; i < 32; i++)
                hreg[i] = __ldcg(&hcur[(long)b * HID + lane + 32 * i]);
            const int o0 = half * 28, o1 = half ? INSZ : 28;
            for (int o = o0; o < o1; o++) {
                float s = 0.f;
#pragma unroll
                for (int i = 0; i < 32; i++)
                    s += hreg[i] * fcw[(long)o * HID + lane + 32 * i];
#pragma unroll
                for (int off = 16; off; off >>= 1) s += __shfl_xor_sync(0xffffffffu, s, off);
                if (lane == 0) {
                    float inp = (td == 0) ? dec[(long)b * OUT_STRIDE + o]
                                          : out[(long)b * OUT_STRIDE + (td - 1) * INSZ + o];
                    float v = inp + s + fcb[o];
                    out[(long)b * OUT_STRIDE + td * INSZ + o] = v;
                    if (td < TGT_STEPS - 1) {
                        __nv_bfloat16 hi = __float2bfloat16(v);
                        long x = (long)(td + 1) * BATCH * KPAD + (long)b * KPAD + o;
                        g_decx_h[x] = hi;
                        g_decx_l[x] = __float2bfloat16(v - __bfloat162float(hi));
                    }
                }
            }
            if (td < TGT_STEPS - 1 && half == 1 && lane < KPAD - INSZ) {
                long x = (long)(td + 1) * BATCH * KPAD + (long)b * KPAD + INSZ + lane;
                g_decx_h[x] = __float2bfloat16(0.f);
                g_decx_l[x] = __float2bfloat16(0.f);
            }
            if (t != TOT_STEPS - 1) grid_bar(++nbar * NCTA);
        }
    }
}

// ---------------- prep kernels ----------------
__global__ void split_whh_kernel(const float* __restrict__ W) {
    long i = blockIdx.x * 256 + threadIdx.x;
    if (i >= (long)NGATE * HID) return;
    float v = W[i];
    __nv_bfloat16 hi = __float2bfloat16(v);
    g_whh_h[i] = hi;
    g_whh_l[i] = __float2bfloat16(v - __bfloat162float(hi));
}
__global__ void split_wih_kernel(const float* __restrict__ W) {
    long i = blockIdx.x * 256 + threadIdx.x;
    if (i >= (long)NGATE * KPAD) return;
    int row = (int)(i >> 6), k = (int)(i & 63);
    float v = (k < INSZ) ? W[(long)row * INSZ + k] : 0.f;
    __nv_bfloat16 hi = __float2bfloat16(v);
    g_wih_h[i] = hi;
    g_wih_l[i] = __float2bfloat16(v - __bfloat162float(hi));
}
__global__ void split_encx_kernel(const float* __restrict__ enc) {
    long i = blockIdx.x * 256 + threadIdx.x;
    if (i >= (long)SRC_STEPS * BATCH * KPAD) return;
    int t = (int)(i / (BATCH * KPAD));
    int r = (int)(i % (BATCH * KPAD));
    int b = r >> 6, k = r & 63;
    float v = (k < INSZ) ? enc[((long)b * 50 + t) * INSZ + k] : 0.f;
    __nv_bfloat16 hi = __float2bfloat16(v);
    g_encx_h[i] = hi;
    g_encx_l[i] = __float2bfloat16(v - __bfloat162float(hi));
}
__global__ void split_decx0_kernel(const float* __restrict__ dec) {
    long i = blockIdx.x * 256 + threadIdx.x;
    if (i >= (long)BATCH * KPAD) return;
    int b = (int)(i >> 6), k = (int)(i & 63);
    float v = (k < INSZ) ? dec[(long)b * OUT_STRIDE + k] : 0.f;
    __nv_bfloat16 hi = __float2bfloat16(v);
    g_decx_h[i] = hi;
    g_decx_l[i] = __float2bfloat16(v - __bfloat162float(hi));
}
__global__ void zero_state_kernel() {
    long i = blockIdx.x * 256 + threadIdx.x;
    if (i == 0) g_bar_ctr = 0;
    if (i >= (long)BATCH * HID) return;
    g_h0[i] = 0.f;
    g_h0h[i] = __float2bfloat16(0.f);
    g_h0l[i] = __float2bfloat16(0.f);
}

extern "C" void kernel_launch(void* const* d_in, const int* in_sizes, int n_in,
                              void* d_out, int out_size)
{
    const float* enc = (const float*)d_in[0];
    const float* dec = (const float*)d_in[1];
    const float* Wih = (const float*)d_in[2];
    const float* Whh = (const float*)d_in[3];
    const float* bih = (const float*)d_in[4];
    const float* bhh = (const float*)d_in[5];
    const float* fcw = (const float*)d_in[6];
    const float* fcb = (const float*)d_in[7];
    float* out = (float*)d_out;

    cudaFuncSetAttribute(seq2seq_persistent,
                         cudaFuncAttributeMaxDynamicSharedMemorySize, SMEM_BYTES);

    split_whh_kernel<<<(NGATE * HID + 255) / 256, 256>>>(Whh);
    split_wih_kernel<<<(NGATE * KPAD + 255) / 256, 256>>>(Wih);
    split_encx_kernel<<<(SRC_STEPS * BATCH * KPAD + 255) / 256, 256>>>(enc);
    split_decx0_kernel<<<(BATCH * KPAD + 255) / 256, 256>>>(dec);
    zero_state_kernel<<<(BATCH * HID + 255) / 256, 256>>>();

    seq2seq_persistent<<<NCTA, 512, SMEM_BYTES>>>(dec, bih, bhh, fcw, fcb, out);
}

// round 7
// speedup vs baseline: 3.0024x; 1.4141x over previous
#include <cuda_runtime.h>
#include <cuda_fp16.h>
#include <cstdint>
#include <math.h>

#define BATCH 1024
#define HID   1024
#define NGATE 3072
#define INSZ  55
#define KPAD  64
#define SRC_STEPS 49
#define TGT_STEPS 25
#define TOT_STEPS 74
#define OUT_STRIDE (TGT_STEPS * INSZ)   // 1375
#define NCTA 128

// ---------------- device scratch (no allocs allowed) ----------------
__device__ __align__(16) float g_h0[BATCH * HID];
__device__ __align__(16) float g_h1[BATCH * HID];
__device__ __align__(16) __half g_h0h[BATCH * HID];
__device__ __align__(16) __half g_h0l[BATCH * HID];
__device__ __align__(16) __half g_h1h[BATCH * HID];
__device__ __align__(16) __half g_h1l[BATCH * HID];
__device__ __align__(16) __half g_whh_h[NGATE * HID];   // fp16 hi of Whh
__device__ __align__(16) __half g_wih_h[NGATE * KPAD];  // fp16 hi of Wih
__device__ __align__(16) __half g_encx_h[SRC_STEPS * BATCH * KPAD];
__device__ __align__(16) __half g_encx_l[SRC_STEPS * BATCH * KPAD];
__device__ __align__(16) __half g_decx_h[TGT_STEPS * BATCH * KPAD];
__device__ __align__(16) __half g_decx_l[TGT_STEPS * BATCH * KPAD];
__device__ __align__(16) float g_gin[BATCH * HID];   // i_n = x@Wih_n partials
__device__ int g_bar_ctr;

// NOTE on compensation scheme: result = (ah+al)·bh where bh is the fp16
// rounding of W (dropped W residual ~2^-11 rel) and ah/al give the
// activation full fp32 precision. Symmetric scheme (a_hi·b_hi + a_hi·b_lo)
// would be equivalent cost; we split the ACTIVATION because h feeds back
// recursively and its error compounds, while W error is static.

// ---------------- PTX helpers (sm_80-class; valid on base sm_103) ----------
__device__ __forceinline__ uint32_t smem_u32(const void* p) {
    uint32_t a;
    asm("{ .reg .u64 t; cvta.to.shared.u64 t, %1; cvt.u32.u64 %0, t; }" : "=r"(a) : "l"(p));
    return a;
}
__device__ __forceinline__ void cp16(uint32_t dst, const void* src) {
    asm volatile("cp.async.cg.shared.global [%0], [%1], 16;"
                 :: "r"(dst), "l"(__cvta_generic_to_global(src)) : "memory");
}
#define CP_COMMIT() asm volatile("cp.async.commit_group;" ::: "memory")
#define CP_WAIT(n)  asm volatile("cp.async.wait_group %0;" :: "n"(n) : "memory")

__device__ __forceinline__ void ldsm4(uint32_t* r, uint32_t addr) {
    asm volatile("ldmatrix.sync.aligned.m8n8.x4.shared.b16 {%0,%1,%2,%3}, [%4];"
        : "=r"(r[0]), "=r"(r[1]), "=r"(r[2]), "=r"(r[3]) : "r"(addr));
}
__device__ __forceinline__ void mma16816(float* c, const uint32_t* a, uint32_t b0, uint32_t b1) {
    asm volatile("mma.sync.aligned.m16n8k16.row.col.f32.f16.f16.f32 "
        "{%0,%1,%2,%3}, {%4,%5,%6,%7}, {%8,%9}, {%0,%1,%2,%3};"
        : "+f"(c[0]), "+f"(c[1]), "+f"(c[2]), "+f"(c[3])
        : "r"(a[0]), "r"(a[1]), "r"(a[2]), "r"(a[3]), "r"(b0), "r"(b1));
}

// ---------------- geometry ----------------
// CTA: 128 batch rows x 64 hidden cols (= 192 gate-cols). 512 thr, 16 warps.
// warpM = wid&7 (16 rows), warpN = wid>>3 (96 gate-cols). All warps active.
// Stage K=32: A hi (10240) + A lo (10240) + B hi (15360) = 35840 B.
#define ROWB 80
#define OFF_AL 10240
#define OFF_B  20480
#define STAGE  35840
#define NSTAGES 34              // 2 Wih (K=64) first, then 32 Whh (K=1024)
#define EPW 200
#define EP_OFF 71680
#define SMEM_BYTES (EP_OFF + 128 * EPW * 4)   // 174080

__device__ __forceinline__ void grid_bar(int target) {
    __syncthreads();
    if (threadIdx.x == 0) {
        __threadfence();
        atomicAdd(&g_bar_ctr, 1);
        while (*(volatile int*)&g_bar_ctr < target) __nanosleep(64);
    }
    __syncthreads();
}

// ---------------------------------------------------------------------------
// Persistent kernel: all 74 GRU steps + 25 decoder FC steps, one launch.
// ---------------------------------------------------------------------------
__global__ __launch_bounds__(512, 1)
void seq2seq_persistent(const float* __restrict__ dec,
                        const float* __restrict__ bih, const float* __restrict__ bhh,
                        const float* __restrict__ fcw, const float* __restrict__ fcb,
                        float* __restrict__ out)
{
    extern __shared__ char smem[];
    const uint32_t sb = smem_u32(smem);
    const int tid = threadIdx.x;
    const int lane = tid & 31, wid = tid >> 5;
    const int warpM = wid & 7, warpN = wid >> 3;
    const int nT = blockIdx.x & 15, mT = blockIdx.x >> 4;
    const int mBase = mT * 128, nBase = nT * 64;

    float* hf[2] = {g_h0, g_h1};
    __half* hsh[2] = {g_h0h, g_h1h};
    __half* hsl[2] = {g_h0l, g_h1l};

    const int arow = warpM * 16 + (lane & 15);
    const int acolh = (lane >> 4) << 3;
    const int bn = (lane & 7) + ((lane >> 4) << 3);
    const int bkh = ((lane >> 3) & 1) << 3;
    const uint32_t a_lofs = arow * ROWB + acolh * 2;
    const uint32_t b_lofs = (warpN * 96 + bn) * ROWB + bkh * 2;

    int cur = 0, nbar = 0;

    for (int t = 0; t < TOT_STEPS; t++) {
        const __half *ah = hsh[cur], *al = hsl[cur];
        const __half *xh, *xl;
        if (t < SRC_STEPS) {
            xh = g_encx_h + (long)t * BATCH * KPAD;
            xl = g_encx_l + (long)t * BATCH * KPAD;
        } else {
            xh = g_decx_h + (long)(t - SRC_STEPS) * BATCH * KPAD;
            xl = g_decx_l + (long)(t - SRC_STEPS) * BATCH * KPAD;
        }

        float acc[12][4];
#pragma unroll
        for (int i = 0; i < 12; i++)
#pragma unroll
            for (int j = 0; j < 4; j++) acc[i][j] = 0.f;

        // ---- stage loader: it<2 -> Wih/x (k0=it*32); else Whh/h (k0=(it-2)*32)
        auto load_stage = [&](int it) {
            const uint32_t st = sb + (uint32_t)(it & 1) * STAGE;
            const __half *As[2], *Bsrc;
            int astr, bstr, k0;
            if (it < 2) {
                As[0] = xh; As[1] = xl; astr = KPAD;
                Bsrc = g_wih_h; bstr = KPAD;
                k0 = it * 32;
            } else {
                As[0] = ah; As[1] = al; astr = HID;
                Bsrc = g_whh_h; bstr = HID;
                k0 = (it - 2) * 32;
            }
            // A: 2(hi/lo) * 128 rows * 4 chunks = 1024 cp16
#pragma unroll
            for (int i = tid; i < 1024; i += 512) {
                int hl = i >> 9, rem = i & 511, row = rem >> 2, c = rem & 3;
                cp16(st + hl * OFF_AL + row * ROWB + c * 16,
                     As[hl] + (long)(mBase + row) * astr + k0 + c * 8);
            }
            // B: 192 rows * 4 chunks = 768 cp16 (hi only)
#pragma unroll
            for (int i = tid; i < 768; i += 512) {
                int grow = i >> 2, c = i & 3;
                long wrow = (long)((grow >> 6) * HID + nBase + (grow & 63));
                cp16(st + OFF_B + grow * ROWB + c * 16,
                     Bsrc + wrow * bstr + k0 + c * 8);
            }
            CP_COMMIT();
        };

        load_stage(0);
        for (int it = 0; it < NSTAGES; it++) {
            if (it + 1 < NSTAGES) { load_stage(it + 1); CP_WAIT(1); }
            else                  { CP_WAIT(0); }
            __syncthreads();

            // ---- compute stage: 2 passes (Ah·B, Al·B) ----
            {
                const uint32_t st = sb + (uint32_t)(it & 1) * STAGE;
                const uint32_t Bh_b = st + OFF_B;
#pragma unroll
                for (int kb = 0; kb < 2; kb++) {
                    uint32_t Ahf[4], Alf[4];
                    uint32_t ao = st + a_lofs + kb * 32;
                    ldsm4(Ahf, ao);
                    ldsm4(Alf, ao + OFF_AL);
                    const uint32_t bo = b_lofs + kb * 32;
                    uint32_t Bf[6][4];
#pragma unroll
                    for (int g = 0; g < 6; g++) ldsm4(Bf[g], Bh_b + bo + g * (16 * ROWB));
#pragma unroll
                    for (int g = 0; g < 6; g++) {
                        mma16816(acc[g * 2],     Ahf, Bf[g][0], Bf[g][1]);
                        mma16816(acc[g * 2 + 1], Ahf, Bf[g][2], Bf[g][3]);
                    }
#pragma unroll
                    for (int g = 0; g < 6; g++) {
                        mma16816(acc[g * 2],     Alf, Bf[g][0], Bf[g][1]);
                        mma16816(acc[g * 2 + 1], Alf, Bf[g][2], Bf[g][3]);
                    }
                }
            }

            // after the 2 Wih stages: stash i_n (gate-cols 128..191), reuse regs
            if (it == 1 && warpN == 1) {
                const int r0 = warpM * 16 + (lane >> 2);
#pragma unroll
                for (int nf = 4; nf < 12; nf++) {
                    int j = nBase + nf * 8 - 32 + (lane & 3) * 2;
                    *(float2*)&g_gin[(long)(mBase + r0) * HID + j] =
                        make_float2(acc[nf][0], acc[nf][1]);
                    *(float2*)&g_gin[(long)(mBase + r0 + 8) * HID + j] =
                        make_float2(acc[nf][2], acc[nf][3]);
                    acc[nf][0] = acc[nf][1] = acc[nf][2] = acc[nf][3] = 0.f;
                }
            }
            __syncthreads();
        }

        // ---- epilogue: frags -> ep smem, gates, h update ----
        float* ep = (float*)(smem + EP_OFF);
        {
            const int r0 = warpM * 16 + (lane >> 2);
#pragma unroll
            for (int nf = 0; nf < 12; nf++) {
                int c = warpN * 96 + nf * 8 + (lane & 3) * 2;
                *(float2*)&ep[r0 * EPW + c]       = make_float2(acc[nf][0], acc[nf][1]);
                *(float2*)&ep[(r0 + 8) * EPW + c] = make_float2(acc[nf][2], acc[nf][3]);
            }
        }
        __syncthreads();

        {
            const float* h_in = hf[cur];
            float* h_out = hf[cur ^ 1];
            __half* hoh = hsh[cur ^ 1];
            __half* hol = hsl[cur ^ 1];
            for (int i = tid; i < 8192; i += 512) {
                int m = i >> 6, j = i & 63;
                int n = nBase + j;
                long gm = mBase + m;
                float pr = ep[m * EPW + j]        + bih[n] + bhh[n];
                float pz = ep[m * EPW + 64 + j]   + bih[HID + n] + bhh[HID + n];
                float ph = ep[m * EPW + 128 + j]  + bhh[2 * HID + n];
                float pi = g_gin[gm * HID + n]    + bih[2 * HID + n];
                float r = 1.f / (1.f + expf(-pr));
                float z = 1.f / (1.f + expf(-pz));
                float nn = tanhf(pi + r * ph);
                float hprev = __ldcg(&h_in[gm * HID + n]);
                float ho = (1.f - z) * nn + z * hprev;
                h_out[gm * HID + n] = ho;
                __half hi = __float2half_rn(ho);
                hoh[gm * HID + n] = hi;
                hol[gm * HID + n] = __float2half_rn(ho - __half2float(hi));
            }
        }
        cur ^= 1;
        grid_bar(++nbar * NCTA);

        // ---- decoder FC ----
        if (t >= SRC_STEPS) {
            const int td = t - SRC_STEPS;
            const float* hcur = hf[cur];
            const int b = blockIdx.x * 8 + (wid >> 1);
            const int half = wid & 1;
            float hreg[32];
#pragma unroll
            for (int i = 0; i < 32; i++)
                hreg[i] = __ldcg(&hcur[(long)b * HID + lane + 32 * i]);
            const int o0 = half * 28, o1 = half ? INSZ : 28;
            for (int o = o0; o < o1; o++) {
                float s = 0.f;
#pragma unroll
                for (int i = 0; i < 32; i++)
                    s += hreg[i] * fcw[(long)o * HID + lane + 32 * i];
#pragma unroll
                for (int off = 16; off; off >>= 1) s += __shfl_xor_sync(0xffffffffu, s, off);
                if (lane == 0) {
                    float inp = (td == 0) ? dec[(long)b * OUT_STRIDE + o]
                                          : out[(long)b * OUT_STRIDE + (td - 1) * INSZ + o];
                    float v = inp + s + fcb[o];
                    out[(long)b * OUT_STRIDE + td * INSZ + o] = v;
                    if (td < TGT_STEPS - 1) {
                        __half hi = __float2half_rn(v);
                        long x = (long)(td + 1) * BATCH * KPAD + (long)b * KPAD + o;
                        g_decx_h[x] = hi;
                        g_decx_l[x] = __float2half_rn(v - __half2float(hi));
                    }
                }
            }
            if (td < TGT_STEPS - 1 && half == 1 && lane < KPAD - INSZ) {
                long x = (long)(td + 1) * BATCH * KPAD + (long)b * KPAD + INSZ + lane;
                g_decx_h[x] = __float2half_rn(0.f);
                g_decx_l[x] = __float2half_rn(0.f);
            }
            if (t != TOT_STEPS - 1) grid_bar(++nbar * NCTA);
        }
    }
}

// ---------------- prep kernels ----------------
__global__ void split_whh_kernel(const float* __restrict__ W) {
    long i = blockIdx.x * 256 + threadIdx.x;
    if (i >= (long)NGATE * HID) return;
    g_whh_h[i] = __float2half_rn(W[i]);
}
__global__ void split_wih_kernel(const float* __restrict__ W) {
    long i = blockIdx.x * 256 + threadIdx.x;
    if (i >= (long)NGATE * KPAD) return;
    int row = (int)(i >> 6), k = (int)(i & 63);
    float v = (k < INSZ) ? W[(long)row * INSZ + k] : 0.f;
    g_wih_h[i] = __float2half_rn(v);
}
__global__ void split_encx_kernel(const float* __restrict__ enc) {
    long i = blockIdx.x * 256 + threadIdx.x;
    if (i >= (long)SRC_STEPS * BATCH * KPAD) return;
    int t = (int)(i / (BATCH * KPAD));
    int r = (int)(i % (BATCH * KPAD));
    int b = r >> 6, k = r & 63;
    float v = (k < INSZ) ? enc[((long)b * 50 + t) * INSZ + k] : 0.f;
    __half hi = __float2half_rn(v);
    g_encx_h[i] = hi;
    g_encx_l[i] = __float2half_rn(v - __half2float(hi));
}
__global__ void split_decx0_kernel(const float* __restrict__ dec) {
    long i = blockIdx.x * 256 + threadIdx.x;
    if (i >= (long)BATCH * KPAD) return;
    int b = (int)(i >> 6), k = (int)(i & 63);
    float v = (k < INSZ) ? dec[(long)b * OUT_STRIDE + k] : 0.f;
    __half hi = __float2half_rn(v);
    g_decx_h[i] = hi;
    g_decx_l[i] = __float2half_rn(v - __half2float(hi));
}
__global__ void zero_state_kernel() {
    long i = blockIdx.x * 256 + threadIdx.x;
    if (i == 0) g_bar_ctr = 0;
    if (i >= (long)BATCH * HID) return;
    g_h0[i] = 0.f;
    g_h0h[i] = __float2half_rn(0.f);
    g_h0l[i] = __float2half_rn(0.f);
}

extern "C" void kernel_launch(void* const* d_in, const int* in_sizes, int n_in,
                              void* d_out, int out_size)
{
    const float* enc = (const float*)d_in[0];
    const float* dec = (const float*)d_in[1];
    const float* Wih = (const float*)d_in[2];
    const float* Whh = (const float*)d_in[3];
    const float* bih = (const float*)d_in[4];
    const float* bhh = (const float*)d_in[5];
    const float* fcw = (const float*)d_in[6];
    const float* fcb = (const float*)d_in[7];
    float* out = (float*)d_out;

    cudaFuncSetAttribute(seq2seq_persistent,
                         cudaFuncAttributeMaxDynamicSharedMemorySize, SMEM_BYTES);

    split_whh_kernel<<<(NGATE * HID + 255) / 256, 256>>>(Whh);
    split_wih_kernel<<<(NGATE * KPAD + 255) / 256, 256>>>(Wih);
    split_encx_kernel<<<(SRC_STEPS * BATCH * KPAD + 255) / 256, 256>>>(enc);
    split_decx0_kernel<<<(BATCH * KPAD + 255) / 256, 256>>>(dec);
    zero_state_kernel<<<(BATCH * HID + 255) / 256, 256>>>();

    seq2seq_persistent<<<NCTA, 512, SMEM_BYTES>>>(dec, bih, bhh, fcw, fcb, out);
}

// round 8
// speedup vs baseline: 4.5822x; 1.5262x over previous
#include <cuda_runtime.h>
#include <cuda_fp16.h>
#include <cstdint>
#include <math.h>

#define BATCH 1024
#define HID   1024
#define NGATE 3072
#define INSZ  55
#define KPAD  64
#define SRC_STEPS 49
#define TGT_STEPS 25
#define TOT_STEPS 74
#define OUT_STRIDE (TGT_STEPS * INSZ)   // 1375
#define NCTA 128

// ---------------- device scratch (no allocs allowed) ----------------
__device__ __align__(16) float g_h0[BATCH * HID];
__device__ __align__(16) float g_h1[BATCH * HID];
__device__ __align__(16) __half g_h0h[BATCH * HID];
__device__ __align__(16) __half g_h1h[BATCH * HID];
__device__ __align__(16) __half g_whh_h[NGATE * HID];   // fp16 Whh
__device__ __align__(16) __half g_wih_h[NGATE * KPAD];  // fp16 Wih (padded K)
__device__ __align__(16) __half g_encx_h[SRC_STEPS * BATCH * KPAD];
__device__ __align__(16) __half g_decx_h[TGT_STEPS * BATCH * KPAD];
__device__ __align__(16) float g_gin[BATCH * HID];      // i_n = x@Wih_n partials
__device__ int g_bar_ctr;

// ---------------- PTX helpers (sm_80-class; valid on base sm_103) ----------
__device__ __forceinline__ uint32_t smem_u32(const void* p) {
    uint32_t a;
    asm("{ .reg .u64 t; cvta.to.shared.u64 t, %1; cvt.u32.u64 %0, t; }" : "=r"(a) : "l"(p));
    return a;
}
__device__ __forceinline__ void cp16(uint32_t dst, const void* src) {
    asm volatile("cp.async.cg.shared.global [%0], [%1], 16;"
                 :: "r"(dst), "l"(__cvta_generic_to_global(src)) : "memory");
}
#define CP_COMMIT() asm volatile("cp.async.commit_group;" ::: "memory")
#define CP_WAIT(n)  asm volatile("cp.async.wait_group %0;" :: "n"(n) : "memory")

__device__ __forceinline__ void ldsm4(uint32_t* r, uint32_t addr) {
    asm volatile("ldmatrix.sync.aligned.m8n8.x4.shared.b16 {%0,%1,%2,%3}, [%4];"
        : "=r"(r[0]), "=r"(r[1]), "=r"(r[2]), "=r"(r[3]) : "r"(addr));
}
__device__ __forceinline__ void mma16816(float* c, const uint32_t* a, uint32_t b0, uint32_t b1) {
    asm volatile("mma.sync.aligned.m16n8k16.row.col.f32.f16.f16.f32 "
        "{%0,%1,%2,%3}, {%4,%5,%6,%7}, {%8,%9}, {%0,%1,%2,%3};"
        : "+f"(c[0]), "+f"(c[1]), "+f"(c[2]), "+f"(c[3])
        : "r"(a[0]), "r"(a[1]), "r"(a[2]), "r"(a[3]), "r"(b0), "r"(b1));
}

// ---------------- geometry ----------------
// CTA: 128 batch rows x 64 hidden cols (= 192 gate-cols). 512 thr, 16 warps.
// warpM = wid&7 (16 rows), warpN = wid>>3 (96 gate-cols). All warps active.
// Stage K=64: A (128 rows x 144B) + B (192 rows x 144B). 17 stages/step:
//   stage 0 = Wih/x (K=64), stages 1..16 = Whh/h (K=1024).
#define ROWB 144                 // 64 halves = 128B data + 16B pad
#define OFF_B 18432              // A tile bytes = 128*144
#define STAGE 46080              // + B tile 192*144 = 27648
#define NSTAGES 17
#define EPW 200
#define EP_OFF 92160
#define SMEM_BYTES (EP_OFF + 128 * EPW * 4)   // 194560

__device__ __forceinline__ void grid_bar(int target) {
    __syncthreads();
    if (threadIdx.x == 0) {
        __threadfence();
        atomicAdd(&g_bar_ctr, 1);
        while (*(volatile int*)&g_bar_ctr < target) __nanosleep(64);
    }
    __syncthreads();
}

// ---------------------------------------------------------------------------
// Persistent kernel: all 74 GRU steps + 25 decoder FC steps, one launch.
// ---------------------------------------------------------------------------
__global__ __launch_bounds__(512, 1)
void seq2seq_persistent(const float* __restrict__ dec,
                        const float* __restrict__ bih, const float* __restrict__ bhh,
                        const float* __restrict__ fcw, const float* __restrict__ fcb,
                        float* __restrict__ out)
{
    extern __shared__ char smem[];
    const uint32_t sb = smem_u32(smem);
    const int tid = threadIdx.x;
    const int lane = tid & 31, wid = tid >> 5;
    const int warpM = wid & 7, warpN = wid >> 3;
    const int nT = blockIdx.x & 15, mT = blockIdx.x >> 4;
    const int mBase = mT * 128, nBase = nT * 64;

    float* hf[2] = {g_h0, g_h1};
    __half* hsh[2] = {g_h0h, g_h1h};

    const int arow = warpM * 16 + (lane & 15);
    const int acolh = (lane >> 4) << 3;
    const int bn = (lane & 7) + ((lane >> 4) << 3);
    const int bkh = ((lane >> 3) & 1) << 3;
    const uint32_t a_lofs = arow * ROWB + acolh * 2;
    const uint32_t b_lofs = (warpN * 96 + bn) * ROWB + bkh * 2;

    int cur = 0, nbar = 0;

    for (int t = 0; t < TOT_STEPS; t++) {
        const __half* ah = hsh[cur];
        const __half* xh = (t < SRC_STEPS)
            ? g_encx_h + (long)t * BATCH * KPAD
            : g_decx_h + (long)(t - SRC_STEPS) * BATCH * KPAD;

        float acc[12][4];
#pragma unroll
        for (int i = 0; i < 12; i++)
#pragma unroll
            for (int j = 0; j < 4; j++) acc[i][j] = 0.f;

        // ---- stage loader: it==0 -> Wih/x (K=64); else Whh/h k0=(it-1)*64
        auto load_stage = [&](int it) {
            const uint32_t st = sb + (uint32_t)(it & 1) * STAGE;
            const __half *Asrc, *Bsrc;
            int astr, bstr, k0;
            if (it == 0) {
                Asrc = xh; astr = KPAD;
                Bsrc = g_wih_h; bstr = KPAD;
                k0 = 0;
            } else {
                Asrc = ah; astr = HID;
                Bsrc = g_whh_h; bstr = HID;
                k0 = (it - 1) * 64;
            }
            // A: 128 rows * 8 chunks = 1024 cp16
#pragma unroll
            for (int i = tid; i < 1024; i += 512) {
                int row = i >> 3, c = i & 7;
                cp16(st + row * ROWB + c * 16,
                     Asrc + (long)(mBase + row) * astr + k0 + c * 8);
            }
            // B: 192 rows * 8 chunks = 1536 cp16
#pragma unroll
            for (int i = tid; i < 1536; i += 512) {
                int grow = i >> 3, c = i & 7;
                long wrow = (long)((grow >> 6) * HID + nBase + (grow & 63));
                cp16(st + OFF_B + grow * ROWB + c * 16,
                     Bsrc + wrow * bstr + k0 + c * 8);
            }
            CP_COMMIT();
        };

        load_stage(0);
        for (int it = 0; it < NSTAGES; it++) {
            if (it + 1 < NSTAGES) { load_stage(it + 1); CP_WAIT(1); }
            else                  { CP_WAIT(0); }
            __syncthreads();

            // ---- compute stage: K=64 (4 k-blocks of 16), single fp16 pass ----
            {
                const uint32_t st = sb + (uint32_t)(it & 1) * STAGE;
                const uint32_t Bb = st + OFF_B;
#pragma unroll
                for (int kb = 0; kb < 4; kb++) {
                    uint32_t Af[4];
                    ldsm4(Af, st + a_lofs + kb * 32);
                    const uint32_t bo = b_lofs + kb * 32;
                    uint32_t Bf[6][4];
#pragma unroll
                    for (int g = 0; g < 6; g++) ldsm4(Bf[g], Bb + bo + g * (16 * ROWB));
#pragma unroll
                    for (int g = 0; g < 6; g++) {
                        mma16816(acc[g * 2],     Af, Bf[g][0], Bf[g][1]);
                        mma16816(acc[g * 2 + 1], Af, Bf[g][2], Bf[g][3]);
                    }
                }
            }

            // after Wih stage: stash i_n (gate-cols 128..191), zero those accs
            if (it == 0 && warpN == 1) {
                const int r0 = warpM * 16 + (lane >> 2);
#pragma unroll
                for (int nf = 4; nf < 12; nf++) {
                    int j = nBase + nf * 8 - 32 + (lane & 3) * 2;
                    *(float2*)&g_gin[(long)(mBase + r0) * HID + j] =
                        make_float2(acc[nf][0], acc[nf][1]);
                    *(float2*)&g_gin[(long)(mBase + r0 + 8) * HID + j] =
                        make_float2(acc[nf][2], acc[nf][3]);
                    acc[nf][0] = acc[nf][1] = acc[nf][2] = acc[nf][3] = 0.f;
                }
            }
            __syncthreads();
        }

        // ---- epilogue: frags -> ep smem, gates, h update ----
        float* ep = (float*)(smem + EP_OFF);
        {
            const int r0 = warpM * 16 + (lane >> 2);
#pragma unroll
            for (int nf = 0; nf < 12; nf++) {
                int c = warpN * 96 + nf * 8 + (lane & 3) * 2;
                *(float2*)&ep[r0 * EPW + c]       = make_float2(acc[nf][0], acc[nf][1]);
                *(float2*)&ep[(r0 + 8) * EPW + c] = make_float2(acc[nf][2], acc[nf][3]);
            }
        }
        __syncthreads();

        {
            const float* h_in = hf[cur];
            float* h_out = hf[cur ^ 1];
            __half* hoh = hsh[cur ^ 1];
            for (int i = tid; i < 8192; i += 512) {
                int m = i >> 6, j = i & 63;
                int n = nBase + j;
                long gm = mBase + m;
                float pr = ep[m * EPW + j]        + bih[n] + bhh[n];
                float pz = ep[m * EPW + 64 + j]   + bih[HID + n] + bhh[HID + n];
                float ph = ep[m * EPW + 128 + j]  + bhh[2 * HID + n];
                float pi = g_gin[gm * HID + n]    + bih[2 * HID + n];
                float r = 1.f / (1.f + expf(-pr));
                float z = 1.f / (1.f + expf(-pz));
                float nn = tanhf(pi + r * ph);
                float hprev = __ldcg(&h_in[gm * HID + n]);
                float ho = (1.f - z) * nn + z * hprev;
                h_out[gm * HID + n] = ho;
                hoh[gm * HID + n] = __float2half_rn(ho);
            }
        }
        cur ^= 1;
        grid_bar(++nbar * NCTA);

        // ---- decoder FC ----
        if (t >= SRC_STEPS) {
            const int td = t - SRC_STEPS;
            const float* hcur = hf[cur];
            const int b = blockIdx.x * 8 + (wid >> 1);
            const int half = wid & 1;
            float hreg[32];
#pragma unroll
            for (int i = 0; i < 32; i++)
                hreg[i] = __ldcg(&hcur[(long)b * HID + lane + 32 * i]);
            const int o0 = half * 28, o1 = half ? INSZ : 28;
            for (int o = o0; o < o1; o++) {
                float s = 0.f;
#pragma unroll
                for (int i = 0; i < 32; i++)
                    s += hreg[i] * fcw[(long)o * HID + lane + 32 * i];
#pragma unroll
                for (int off = 16; off; off >>= 1) s += __shfl_xor_sync(0xffffffffu, s, off);
                if (lane == 0) {
                    float inp = (td == 0) ? dec[(long)b * OUT_STRIDE + o]
                                          : out[(long)b * OUT_STRIDE + (td - 1) * INSZ + o];
                    float v = inp + s + fcb[o];
                    out[(long)b * OUT_STRIDE + td * INSZ + o] = v;
                    if (td < TGT_STEPS - 1) {
                        long x = (long)(td + 1) * BATCH * KPAD + (long)b * KPAD + o;
                        g_decx_h[x] = __float2half_rn(v);
                    }
                }
            }
            if (td < TGT_STEPS - 1 && half == 1 && lane < KPAD - INSZ) {
                long x = (long)(td + 1) * BATCH * KPAD + (long)b * KPAD + INSZ + lane;
                g_decx_h[x] = __float2half_rn(0.f);
            }
            if (t != TOT_STEPS - 1) grid_bar(++nbar * NCTA);
        }
    }
}

// ---------------- prep kernels ----------------
__global__ void split_whh_kernel(const float* __restrict__ W) {
    long i = blockIdx.x * 256 + threadIdx.x;
    if (i >= (long)NGATE * HID) return;
    g_whh_h[i] = __float2half_rn(W[i]);
}
__global__ void split_wih_kernel(const float* __restrict__ W) {
    long i = blockIdx.x * 256 + threadIdx.x;
    if (i >= (long)NGATE * KPAD) return;
    int row = (int)(i >> 6), k = (int)(i & 63);
    float v = (k < INSZ) ? W[(long)row * INSZ + k] : 0.f;
    g_wih_h[i] = __float2half_rn(v);
}
__global__ void split_encx_kernel(const float* __restrict__ enc) {
    long i = blockIdx.x * 256 + threadIdx.x;
    if (i >= (long)SRC_STEPS * BATCH * KPAD) return;
    int t = (int)(i / (BATCH * KPAD));
    int r = (int)(i % (BATCH * KPAD));
    int b = r >> 6, k = r & 63;
    float v = (k < INSZ) ? enc[((long)b * 50 + t) * INSZ + k] : 0.f;
    g_encx_h[i] = __float2half_rn(v);
}
__global__ void split_decx0_kernel(const float* __restrict__ dec) {
    long i = blockIdx.x * 256 + threadIdx.x;
    if (i >= (long)BATCH * KPAD) return;
    int b = (int)(i >> 6), k = (int)(i & 63);
    float v = (k < INSZ) ? dec[(long)b * OUT_STRIDE + k] : 0.f;
    g_decx_h[i] = __float2half_rn(v);
}
__global__ void zero_state_kernel() {
    long i = blockIdx.x * 256 + threadIdx.x;
    if (i == 0) g_bar_ctr = 0;
    if (i >= (long)BATCH * HID) return;
    g_h0[i] = 0.f;
    g_h0h[i] = __float2half_rn(0.f);
}

extern "C" void kernel_launch(void* const* d_in, const int* in_sizes, int n_in,
                              void* d_out, int out_size)
{
    const float* enc = (const float*)d_in[0];
    const float* dec = (const float*)d_in[1];
    const float* Wih = (const float*)d_in[2];
    const float* Whh = (const float*)d_in[3];
    const float* bih = (const float*)d_in[4];
    const float* bhh = (const float*)d_in[5];
    const float* fcw = (const float*)d_in[6];
    const float* fcb = (const float*)d_in[7];
    float* out = (float*)d_out;

    cudaFuncSetAttribute(seq2seq_persistent,
                         cudaFuncAttributeMaxDynamicSharedMemorySize, SMEM_BYTES);

    split_whh_kernel<<<(NGATE * HID + 255) / 256, 256>>>(Whh);
    split_wih_kernel<<<(NGATE * KPAD + 255) / 256, 256>>>(Wih);
    split_encx_kernel<<<(SRC_STEPS * BATCH * KPAD + 255) / 256, 256>>>(enc);
    split_decx0_kernel<<<(BATCH * KPAD + 255) / 256, 256>>>(dec);
    zero_state_kernel<<<(BATCH * HID + 255) / 256, 256>>>();

    seq2seq_persistent<<<NCTA, 512, SMEM_BYTES>>>(dec, bih, bhh, fcw, fcb, out);
}

// round 9
// speedup vs baseline: 5.2905x; 1.1546x over previous
#include <cuda_runtime.h>
#include <cuda_fp16.h>
#include <cstdint>
#include <math.h>

#define BATCH 1024
#define HID   1024
#define NGATE 3072
#define INSZ  55
#define KPAD  64
#define SRC_STEPS 49
#define TGT_STEPS 25
#define TOT_STEPS 74
#define OUT_STRIDE (TGT_STEPS * INSZ)   // 1375
#define NCTA 128

// ---------------- device scratch (no allocs allowed) ----------------
__device__ __align__(16) float g_h0[BATCH * HID];
__device__ __align__(16) float g_h1[BATCH * HID];
__device__ __align__(16) __half g_h0h[BATCH * HID];
__device__ __align__(16) __half g_h1h[BATCH * HID];
__device__ __align__(16) __half g_whh_h[NGATE * HID];   // fp16 Whh
__device__ __align__(16) __half g_wih_h[NGATE * KPAD];  // fp16 Wih (padded K)
__device__ __align__(16) __half g_encx_h[SRC_STEPS * BATCH * KPAD];
__device__ __align__(16) __half g_decx_h[TGT_STEPS * BATCH * KPAD];
__device__ int g_bar_ctr;

// ---------------- PTX helpers (sm_80-class; valid on base sm_103) ----------
__device__ __forceinline__ uint32_t smem_u32(const void* p) {
    uint32_t a;
    asm("{ .reg .u64 t; cvta.to.shared.u64 t, %1; cvt.u32.u64 %0, t; }" : "=r"(a) : "l"(p));
    return a;
}
__device__ __forceinline__ void cp16(uint32_t dst, const void* src) {
    asm volatile("cp.async.cg.shared.global [%0], [%1], 16;"
                 :: "r"(dst), "l"(__cvta_generic_to_global(src)) : "memory");
}
#define CP_COMMIT() asm volatile("cp.async.commit_group;" ::: "memory")
#define CP_WAIT(n)  asm volatile("cp.async.wait_group %0;" :: "n"(n) : "memory")

__device__ __forceinline__ void ldsm4(uint32_t* r, uint32_t addr) {
    asm volatile("ldmatrix.sync.aligned.m8n8.x4.shared.b16 {%0,%1,%2,%3}, [%4];"
        : "=r"(r[0]), "=r"(r[1]), "=r"(r[2]), "=r"(r[3]) : "r"(addr));
}
__device__ __forceinline__ void mma16816(float* c, const uint32_t* a, uint32_t b0, uint32_t b1) {
    asm volatile("mma.sync.aligned.m16n8k16.row.col.f32.f16.f16.f32 "
        "{%0,%1,%2,%3}, {%4,%5,%6,%7}, {%8,%9}, {%0,%1,%2,%3};"
        : "+f"(c[0]), "+f"(c[1]), "+f"(c[2]), "+f"(c[3])
        : "r"(a[0]), "r"(a[1]), "r"(a[2]), "r"(a[3]), "r"(b0), "r"(b1));
}

__device__ __forceinline__ float fsig(float x) {
    return __fdividef(1.f, 1.f + __expf(-x));
}
__device__ __forceinline__ float ftanh(float x) {
    return 1.f - __fdividef(2.f, __expf(2.f * x) + 1.f);
}

// ---------------- geometry ----------------
// CTA: 128 batch rows x 64 hidden cols (= 192 gate-cols). 512 thr, 16 warps.
// warpM = wid&7 (16 rows), warpN = wid>>3 (96 gate-cols). All warps active.
// Stage K=128 (stage 0: K=64 Wih). 9 stages/step.
// ROWB=272 (256B data + 16B pad; row stride = 68 words == 4 banks mod 32 ->
// ldsm conflict-free). A tile 128*272=34816, B tile 192*272=52224.
#define ROWB 272
#define OFF_B 34816
#define STAGE 87040
#define NSTAGES 9
#define EPW 200                 // epilogue fp32 tile, ALIASED onto stage bufs
#define GIN_OFF (2 * STAGE)     // 174080: smem i_n stash 128 x GINW fp32
#define GINW 66
#define SMEM_BYTES (GIN_OFF + 128 * GINW * 4)   // 207872

__device__ __forceinline__ void grid_bar(int target) {
    __syncthreads();
    if (threadIdx.x == 0) {
        __threadfence();
        atomicAdd(&g_bar_ctr, 1);
        while (*(volatile int*)&g_bar_ctr < target) __nanosleep(32);
    }
    __syncthreads();
}

// ---------------------------------------------------------------------------
// Persistent kernel: all 74 GRU steps + 25 decoder FC steps, one launch.
// ---------------------------------------------------------------------------
__global__ __launch_bounds__(512, 1)
void seq2seq_persistent(const float* __restrict__ dec,
                        const float* __restrict__ bih, const float* __restrict__ bhh,
                        const float* __restrict__ fcw, const float* __restrict__ fcb,
                        float* __restrict__ out)
{
    extern __shared__ char smem[];
    const uint32_t sb = smem_u32(smem);
    const int tid = threadIdx.x;
    const int lane = tid & 31, wid = tid >> 5;
    const int warpM = wid & 7, warpN = wid >> 3;
    const int nT = blockIdx.x & 15, mT = blockIdx.x >> 4;
    const int mBase = mT * 128, nBase = nT * 64;

    float* hf[2] = {g_h0, g_h1};
    __half* hsh[2] = {g_h0h, g_h1h};
    float* sgin = (float*)(smem + GIN_OFF);

    const int arow = warpM * 16 + (lane & 15);
    const int acolh = (lane >> 4) << 3;
    const int bn = (lane & 7) + ((lane >> 4) << 3);
    const int bkh = ((lane >> 3) & 1) << 3;
    const uint32_t a_lofs = arow * ROWB + acolh * 2;
    const uint32_t b_lofs = (warpN * 96 + bn) * ROWB + bkh * 2;

    int cur = 0, nbar = 0;

    for (int t = 0; t < TOT_STEPS; t++) {
        const __half* ah = hsh[cur];
        const __half* xh = (t < SRC_STEPS)
            ? g_encx_h + (long)t * BATCH * KPAD
            : g_decx_h + (long)(t - SRC_STEPS) * BATCH * KPAD;

        float acc[12][4];
#pragma unroll
        for (int i = 0; i < 12; i++)
#pragma unroll
            for (int j = 0; j < 4; j++) acc[i][j] = 0.f;

        // ---- stage loader: it==0 -> Wih/x (K=64); else Whh/h k0=(it-1)*128
        auto load_stage = [&](int it) {
            const uint32_t st = sb + (uint32_t)(it & 1) * STAGE;
            if (it == 0) {
#pragma unroll
                for (int i = tid; i < 1024; i += 512) {          // A: 128r x 8c
                    int row = i >> 3, c = i & 7;
                    cp16(st + row * ROWB + c * 16,
                         xh + (long)(mBase + row) * KPAD + c * 8);
                }
#pragma unroll
                for (int i = tid; i < 1536; i += 512) {          // B: 192r x 8c
                    int grow = i >> 3, c = i & 7;
                    long wrow = (long)((grow >> 6) * HID + nBase + (grow & 63));
                    cp16(st + OFF_B + grow * ROWB + c * 16,
                         g_wih_h + wrow * KPAD + c * 8);
                }
            } else {
                const int k0 = (it - 1) * 128;
#pragma unroll
                for (int i = tid; i < 2048; i += 512) {          // A: 128r x 16c
                    int row = i >> 4, c = i & 15;
                    cp16(st + row * ROWB + c * 16,
                         ah + (long)(mBase + row) * HID + k0 + c * 8);
                }
#pragma unroll
                for (int i = tid; i < 3072; i += 512) {          // B: 192r x 16c
                    int grow = i >> 4, c = i & 15;
                    long wrow = (long)((grow >> 6) * HID + nBase + (grow & 63));
                    cp16(st + OFF_B + grow * ROWB + c * 16,
                         g_whh_h + wrow * HID + k0 + c * 8);
                }
            }
            CP_COMMIT();
        };

        load_stage(0);
        for (int it = 0; it < NSTAGES; it++) {
            if (it + 1 < NSTAGES) { load_stage(it + 1); CP_WAIT(1); }
            else                  { CP_WAIT(0); }
            __syncthreads();

            // ---- compute stage: single fp16 pass ----
            {
                const uint32_t st = sb + (uint32_t)(it & 1) * STAGE;
                const uint32_t Bb = st + OFF_B;
                const int nkb = (it == 0) ? 4 : 8;
                for (int kb = 0; kb < nkb; kb++) {
                    uint32_t Af[4];
                    ldsm4(Af, st + a_lofs + kb * 32);
                    const uint32_t bo = b_lofs + kb * 32;
                    uint32_t Bf[6][4];
#pragma unroll
                    for (int g = 0; g < 6; g++) ldsm4(Bf[g], Bb + bo + g * (16 * ROWB));
#pragma unroll
                    for (int g = 0; g < 6; g++) {
                        mma16816(acc[g * 2],     Af, Bf[g][0], Bf[g][1]);
                        mma16816(acc[g * 2 + 1], Af, Bf[g][2], Bf[g][3]);
                    }
                }
            }

            // after Wih stage: stash i_n (gate-cols 128..191) to SMEM, zero accs
            if (it == 0 && warpN == 1) {
                const int r0 = warpM * 16 + (lane >> 2);
#pragma unroll
                for (int nf = 4; nf < 12; nf++) {
                    int jl = nf * 8 - 32 + (lane & 3) * 2;      // 0..62
                    *(float2*)&sgin[r0 * GINW + jl] =
                        make_float2(acc[nf][0], acc[nf][1]);
                    *(float2*)&sgin[(r0 + 8) * GINW + jl] =
                        make_float2(acc[nf][2], acc[nf][3]);
                    acc[nf][0] = acc[nf][1] = acc[nf][2] = acc[nf][3] = 0.f;
                }
            }
            __syncthreads();
        }

        // ---- epilogue: frags -> ep smem (aliases stage bufs), gates, h ----
        float* ep = (float*)smem;
        {
            const int r0 = warpM * 16 + (lane >> 2);
#pragma unroll
            for (int nf = 0; nf < 12; nf++) {
                int c = warpN * 96 + nf * 8 + (lane & 3) * 2;
                *(float2*)&ep[r0 * EPW + c]       = make_float2(acc[nf][0], acc[nf][1]);
                *(float2*)&ep[(r0 + 8) * EPW + c] = make_float2(acc[nf][2], acc[nf][3]);
            }
        }
        __syncthreads();

        {
            const float* h_in = hf[cur];
            float* h_out = hf[cur ^ 1];
            __half* hoh = hsh[cur ^ 1];
            for (int i = tid; i < 8192; i += 512) {
                int m = i >> 6, j = i & 63;
                int n = nBase + j;
                long gm = mBase + m;
                float pr = ep[m * EPW + j]        + bih[n] + bhh[n];
                float pz = ep[m * EPW + 64 + j]   + bih[HID + n] + bhh[HID + n];
                float ph = ep[m * EPW + 128 + j]  + bhh[2 * HID + n];
                float pi = sgin[m * GINW + j]     + bih[2 * HID + n];
                float r = fsig(pr);
                float z = fsig(pz);
                float nn = ftanh(pi + r * ph);
                float hprev = __ldcg(&h_in[gm * HID + n]);
                float ho = (1.f - z) * nn + z * hprev;
                h_out[gm * HID + n] = ho;
                hoh[gm * HID + n] = __float2half_rn(ho);
            }
        }
        cur ^= 1;
        grid_bar(++nbar * NCTA);

        // ---- decoder FC ----
        if (t >= SRC_STEPS) {
            const int td = t - SRC_STEPS;
            const float* hcur = hf[cur];
            const int b = blockIdx.x * 8 + (wid >> 1);
            const int half = wid & 1;
            float hreg[32];
#pragma unroll
            for (int i = 0; i < 32; i++)
                hreg[i] = __ldcg(&hcur[(long)b * HID + lane + 32 * i]);
            const int o0 = half * 28, o1 = half ? INSZ : 28;
            for (int o = o0; o < o1; o++) {
                float s = 0.f;
#pragma unroll
                for (int i = 0; i < 32; i++)
                    s += hreg[i] * fcw[(long)o * HID + lane + 32 * i];
#pragma unroll
                for (int off = 16; off; off >>= 1) s += __shfl_xor_sync(0xffffffffu, s, off);
                if (lane == 0) {
                    float inp = (td == 0) ? dec[(long)b * OUT_STRIDE + o]
                                          : out[(long)b * OUT_STRIDE + (td - 1) * INSZ + o];
                    float v = inp + s + fcb[o];
                    out[(long)b * OUT_STRIDE + td * INSZ + o] = v;
                    if (td < TGT_STEPS - 1) {
                        long x = (long)(td + 1) * BATCH * KPAD + (long)b * KPAD + o;
                        g_decx_h[x] = __float2half_rn(v);
                    }
                }
            }
            if (td < TGT_STEPS - 1 && half == 1 && lane < KPAD - INSZ) {
                long x = (long)(td + 1) * BATCH * KPAD + (long)b * KPAD + INSZ + lane;
                g_decx_h[x] = __float2half_rn(0.f);
            }
            if (t != TOT_STEPS - 1) grid_bar(++nbar * NCTA);
        }
    }
}

// ---------------- prep kernels ----------------
__global__ void split_whh_kernel(const float* __restrict__ W) {
    long i = blockIdx.x * 256 + threadIdx.x;
    if (i >= (long)NGATE * HID) return;
    g_whh_h[i] = __float2half_rn(W[i]);
}
__global__ void split_wih_kernel(const float* __restrict__ W) {
    long i = blockIdx.x * 256 + threadIdx.x;
    if (i >= (long)NGATE * KPAD) return;
    int row = (int)(i >> 6), k = (int)(i & 63);
    float v = (k < INSZ) ? W[(long)row * INSZ + k] : 0.f;
    g_wih_h[i] = __float2half_rn(v);
}
__global__ void split_encx_kernel(const float* __restrict__ enc) {
    long i = blockIdx.x * 256 + threadIdx.x;
    if (i >= (long)SRC_STEPS * BATCH * KPAD) return;
    int t = (int)(i / (BATCH * KPAD));
    int r = (int)(i % (BATCH * KPAD));
    int b = r >> 6, k = r & 63;
    float v = (k < INSZ) ? enc[((long)b * 50 + t) * INSZ + k] : 0.f;
    g_encx_h[i] = __float2half_rn(v);
}
__global__ void split_decx0_kernel(const float* __restrict__ dec) {
    long i = blockIdx.x * 256 + threadIdx.x;
    if (i >= (long)BATCH * KPAD) return;
    int b = (int)(i >> 6), k = (int)(i & 63);
    float v = (k < INSZ) ? dec[(long)b * OUT_STRIDE + k] : 0.f;
    g_decx_h[i] = __float2half_rn(v);
}
__global__ void zero_state_kernel() {
    long i = blockIdx.x * 256 + threadIdx.x;
    if (i == 0) g_bar_ctr = 0;
    if (i >= (long)BATCH * HID) return;
    g_h0[i] = 0.f;
    g_h0h[i] = __float2half_rn(0.f);
}

extern "C" void kernel_launch(void* const* d_in, const int* in_sizes, int n_in,
                              void* d_out, int out_size)
{
    const float* enc = (const float*)d_in[0];
    const float* dec = (const float*)d_in[1];
    const float* Wih = (const float*)d_in[2];
    const float* Whh = (const float*)d_in[3];
    const float* bih = (const float*)d_in[4];
    const float* bhh = (const float*)d_in[5];
    const float* fcw = (const float*)d_in[6];
    const float* fcb = (const float*)d_in[7];
    float* out = (float*)d_out;

    cudaFuncSetAttribute(seq2seq_persistent,
                         cudaFuncAttributeMaxDynamicSharedMemorySize, SMEM_BYTES);

    split_whh_kernel<<<(NGATE * HID + 255) / 256, 256>>>(Whh);
    split_wih_kernel<<<(NGATE * KPAD + 255) / 256, 256>>>(Wih);
    split_encx_kernel<<<(SRC_STEPS * BATCH * KPAD + 255) / 256, 256>>>(enc);
    split_decx0_kernel<<<(BATCH * KPAD + 255) / 256, 256>>>(dec);
    zero_state_kernel<<<(BATCH * HID + 255) / 256, 256>>>();

    seq2seq_persistent<<<NCTA, 512, SMEM_BYTES>>>(dec, bih, bhh, fcw, fcb, out);
}

// round 10
// speedup vs baseline: 5.5334x; 1.0459x over previous
#include <cuda_runtime.h>
#include <cuda_fp16.h>
#include <cstdint>
#include <math.h>

#define BATCH 1024
#define HID   1024
#define NGATE 3072
#define INSZ  55
#define KPAD  64
#define SRC_STEPS 49
#define TGT_STEPS 25
#define TOT_STEPS 74
#define OUT_STRIDE (TGT_STEPS * INSZ)   // 1375
#define NCTA 128

// ---------------- device scratch (no allocs allowed) ----------------
__device__ __align__(16) float g_h0[BATCH * HID];
__device__ __align__(16) float g_h1[BATCH * HID];
__device__ __align__(16) __half g_h0h[BATCH * HID];
__device__ __align__(16) __half g_h1h[BATCH * HID];
__device__ __align__(16) __half g_whh_h[NGATE * HID];   // fp16 Whh
__device__ __align__(16) __half g_wih_h[NGATE * KPAD];  // fp16 Wih (padded K)
__device__ __align__(16) __half g_encx_h[SRC_STEPS * BATCH * KPAD];
__device__ __align__(16) __half g_decx_h[TGT_STEPS * BATCH * KPAD];
__device__ int g_bar_ctr;

// ---------------- PTX helpers (sm_80-class; valid on base sm_103) ----------
__device__ __forceinline__ uint32_t smem_u32(const void* p) {
    uint32_t a;
    asm("{ .reg .u64 t; cvta.to.shared.u64 t, %1; cvt.u32.u64 %0, t; }" : "=r"(a) : "l"(p));
    return a;
}
__device__ __forceinline__ void cp16(uint32_t dst, const void* src) {
    asm volatile("cp.async.cg.shared.global [%0], [%1], 16;"
                 :: "r"(dst), "l"(__cvta_generic_to_global(src)) : "memory");
}
#define CP_COMMIT() asm volatile("cp.async.commit_group;" ::: "memory")
#define CP_WAIT(n)  asm volatile("cp.async.wait_group %0;" :: "n"(n) : "memory")

__device__ __forceinline__ void ldsm4(uint32_t* r, uint32_t addr) {
    asm volatile("ldmatrix.sync.aligned.m8n8.x4.shared.b16 {%0,%1,%2,%3}, [%4];"
        : "=r"(r[0]), "=r"(r[1]), "=r"(r[2]), "=r"(r[3]) : "r"(addr));
}
__device__ __forceinline__ void mma16816(float* c, const uint32_t* a, uint32_t b0, uint32_t b1) {
    asm volatile("mma.sync.aligned.m16n8k16.row.col.f32.f16.f16.f32 "
        "{%0,%1,%2,%3}, {%4,%5,%6,%7}, {%8,%9}, {%0,%1,%2,%3};"
        : "+f"(c[0]), "+f"(c[1]), "+f"(c[2]), "+f"(c[3])
        : "r"(a[0]), "r"(a[1]), "r"(a[2]), "r"(a[3]), "r"(b0), "r"(b1));
}

__device__ __forceinline__ float fsig(float x) {
    return __fdividef(1.f, 1.f + __expf(-x));
}
__device__ __forceinline__ float ftanh(float x) {
    return 1.f - __fdividef(2.f, __expf(2.f * x) + 1.f);
}

// ---------------- geometry ----------------
// CTA: 128 batch rows x 64 hidden cols (= 192 gate-cols). 512 thr, 16 warps.
// warpM = wid&3 (32 rows), warpN = wid>>2 (48 gate-cols). All warps active.
// Stage K=128 (stage 0: K=64 Wih). 9 stages/step.
// ROWB=272 (256B data + 16B pad): conflict-free ldsm.
#define ROWB 272
#define OFF_B 34816
#define STAGE 87040
#define NSTAGES 9
#define EPW 200                 // epilogue fp32 tile, ALIASED onto stage bufs
#define GIN_OFF (2 * STAGE)     // 174080: smem i_n stash 128 x GINW fp32
#define GINW 66
#define BIAS_OFF (GIN_OFF + 128 * GINW * 4)     // 207872
#define SMEM_BYTES (BIAS_OFF + 4 * 64 * 4)      // 208896

__device__ __forceinline__ void grid_bar(int target) {
    __syncthreads();
    if (threadIdx.x == 0) {
        __threadfence();
        atomicAdd(&g_bar_ctr, 1);
        while (*(volatile int*)&g_bar_ctr < target) __nanosleep(32);
    }
    __syncthreads();
}

// ---------------------------------------------------------------------------
// Persistent kernel: all 74 GRU steps + 25 decoder FC steps, one launch.
// ---------------------------------------------------------------------------
__global__ __launch_bounds__(512, 1)
void seq2seq_persistent(const float* __restrict__ dec,
                        const float* __restrict__ bih, const float* __restrict__ bhh,
                        const float* __restrict__ fcw, const float* __restrict__ fcb,
                        float* __restrict__ out)
{
    extern __shared__ char smem[];
    const uint32_t sb = smem_u32(smem);
    const int tid = threadIdx.x;
    const int lane = tid & 31, wid = tid >> 5;
    const int warpM = wid & 3, warpN = wid >> 2;
    const int nT = blockIdx.x & 15, mT = blockIdx.x >> 4;
    const int mBase = mT * 128, nBase = nT * 64;

    float* hf[2] = {g_h0, g_h1};
    __half* hsh[2] = {g_h0h, g_h1h};
    float* sgin = (float*)(smem + GIN_OFF);
    float* sbias = (float*)(smem + BIAS_OFF);   // [4][64]: r, z, n_hh, n_ih

    // bias precompute (once)
    if (tid < 64) {
        int n = nBase + tid;
        sbias[tid]       = bih[n] + bhh[n];
        sbias[64 + tid]  = bih[HID + n] + bhh[HID + n];
        sbias[128 + tid] = bhh[2 * HID + n];
        sbias[192 + tid] = bih[2 * HID + n];
    }
    __syncthreads();

    // ldsm lane addressing (within stage buffer)
    const int arow = warpM * 32 + (lane & 15);
    const int acolh = (lane >> 4) << 3;
    const int bn = (lane & 7) + ((lane >> 4) << 3);
    const int bkh = ((lane >> 3) & 1) << 3;
    const uint32_t a_lofs = arow * ROWB + acolh * 2;
    const uint32_t b_lofs = (warpN * 48 + bn) * ROWB + bkh * 2;

    int cur = 0, nbar = 0;
    bool pre = false;

    for (int t = 0; t < TOT_STEPS; t++) {
        const __half* ah = hsh[cur];
        const __half* xh = (t < SRC_STEPS)
            ? g_encx_h + (long)t * BATCH * KPAD
            : g_decx_h + (long)(t - SRC_STEPS) * BATCH * KPAD;

        float acc[2][6][4];
#pragma unroll
        for (int a0 = 0; a0 < 2; a0++)
#pragma unroll
            for (int i = 0; i < 6; i++)
#pragma unroll
                for (int j = 0; j < 4; j++) acc[a0][i][j] = 0.f;

        // ---- stage-0 loader (Wih / x) ----
        auto load_stage0 = [&](const __half* xp) {
            const uint32_t st = sb;   // buf 0
#pragma unroll
            for (int i = tid; i < 1024; i += 512) {          // A: 128r x 8c
                int row = i >> 3, c = i & 7;
                cp16(st + row * ROWB + c * 16,
                     xp + (long)(mBase + row) * KPAD + c * 8);
            }
#pragma unroll
            for (int i = tid; i < 1536; i += 512) {          // B: 192r x 8c
                int grow = i >> 3, c = i & 7;
                long wrow = (long)((grow >> 6) * HID + nBase + (grow & 63));
                cp16(st + OFF_B + grow * ROWB + c * 16,
                     g_wih_h + wrow * KPAD + c * 8);
            }
            CP_COMMIT();
        };
        // ---- Whh stage loader (it >= 1) ----
        auto load_stageW = [&](int it) {
            const uint32_t st = sb + (uint32_t)(it & 1) * STAGE;
            const int k0 = (it - 1) * 128;
#pragma unroll
            for (int i = tid; i < 2048; i += 512) {          // A: 128r x 16c
                int row = i >> 4, c = i & 15;
                cp16(st + row * ROWB + c * 16,
                     ah + (long)(mBase + row) * HID + k0 + c * 8);
            }
#pragma unroll
            for (int i = tid; i < 3072; i += 512) {          // B: 192r x 16c
                int grow = i >> 4, c = i & 15;
                long wrow = (long)((grow >> 6) * HID + nBase + (grow & 63));
                cp16(st + OFF_B + grow * ROWB + c * 16,
                     g_whh_h + wrow * HID + k0 + c * 8);
            }
            CP_COMMIT();
        };

        if (!pre) load_stage0(xh);
        for (int it = 0; it < NSTAGES; it++) {
            if (it + 1 < NSTAGES) { load_stageW(it + 1); CP_WAIT(1); }
            else                  { CP_WAIT(0); }
            __syncthreads();

            // ---- compute stage: single fp16 pass, 32Mx48N per warp ----
            {
                const uint32_t st = sb + (uint32_t)(it & 1) * STAGE;
                const uint32_t Bb = st + OFF_B;
                const int nkb = (it == 0) ? 4 : 8;
                for (int kb = 0; kb < nkb; kb++) {
                    uint32_t Af[2][4];
                    ldsm4(Af[0], st + a_lofs + kb * 32);
                    ldsm4(Af[1], st + a_lofs + 16 * ROWB + kb * 32);
                    uint32_t Bf[3][4];
                    const uint32_t bo = Bb + b_lofs + kb * 32;
#pragma unroll
                    for (int g = 0; g < 3; g++) ldsm4(Bf[g], bo + g * (16 * ROWB));
#pragma unroll
                    for (int mf = 0; mf < 2; mf++)
#pragma unroll
                        for (int g = 0; g < 3; g++) {
                            mma16816(acc[mf][g * 2],     Af[mf], Bf[g][0], Bf[g][1]);
                            mma16816(acc[mf][g * 2 + 1], Af[mf], Bf[g][2], Bf[g][3]);
                        }
                }
            }

            // after Wih stage: stash i_n (gate-cols 128..191) to SMEM, zero accs
            if (it == 0) {
                const int r0 = warpM * 32 + (lane >> 2);
#pragma unroll
                for (int mf = 0; mf < 2; mf++)
#pragma unroll
                    for (int j = 0; j < 6; j++) {
                        const int gc = warpN * 48 + j * 8;
                        if (gc >= 128) {
                            int jl = gc - 128 + (lane & 3) * 2;
                            int rr = r0 + mf * 16;
                            *(float2*)&sgin[rr * GINW + jl] =
                                make_float2(acc[mf][j][0], acc[mf][j][1]);
                            *(float2*)&sgin[(rr + 8) * GINW + jl] =
                                make_float2(acc[mf][j][2], acc[mf][j][3]);
                            acc[mf][j][0] = acc[mf][j][1] = 0.f;
                            acc[mf][j][2] = acc[mf][j][3] = 0.f;
                        }
                    }
            }
            __syncthreads();
        }

        // ---- epilogue: frags -> ep smem (aliases stage bufs), gates, h ----
        float* ep = (float*)smem;
        {
            const int r0 = warpM * 32 + (lane >> 2);
#pragma unroll
            for (int mf = 0; mf < 2; mf++)
#pragma unroll
                for (int j = 0; j < 6; j++) {
                    int c = warpN * 48 + j * 8 + (lane & 3) * 2;
                    int rr = r0 + mf * 16;
                    *(float2*)&ep[rr * EPW + c] =
                        make_float2(acc[mf][j][0], acc[mf][j][1]);
                    *(float2*)&ep[(rr + 8) * EPW + c] =
                        make_float2(acc[mf][j][2], acc[mf][j][3]);
                }
        }
        __syncthreads();

        {
            const float* h_in = hf[cur];
            float* h_out = hf[cur ^ 1];
            __half* hoh = hsh[cur ^ 1];
            for (int i = tid; i < 8192; i += 512) {
                int m = i >> 6, j = i & 63;
                int n = nBase + j;
                long gm = mBase + m;
                float pr = ep[m * EPW + j]        + sbias[j];
                float pz = ep[m * EPW + 64 + j]   + sbias[64 + j];
                float ph = ep[m * EPW + 128 + j]  + sbias[128 + j];
                float pi = sgin[m * GINW + j]     + sbias[192 + j];
                float r = fsig(pr);
                float z = fsig(pz);
                float nn = ftanh(pi + r * ph);
                float hprev = h_in[gm * HID + n];   // self-written tile: L1-safe
                float ho = (1.f - z) * nn + z * hprev;
                h_out[gm * HID + n] = ho;
                hoh[gm * HID + n] = __float2half_rn(ho);
            }
        }
        cur ^= 1;
        __syncthreads();   // ep reads done before preload overwrites buf 0

        // ---- preload next step's stage 0 if its x is already materialized ----
        pre = false;
        if (t + 1 < TOT_STEPS && t + 1 <= SRC_STEPS) {
            const __half* xn = (t + 1 < SRC_STEPS)
                ? g_encx_h + (long)(t + 1) * BATCH * KPAD
                : g_decx_h;   // first decoder step: x precomputed
            load_stage0(xn);
            pre = true;
        }

        grid_bar(++nbar * NCTA);

        // ---- decoder FC ----
        if (t >= SRC_STEPS) {
            const int td = t - SRC_STEPS;
            const float* hcur = hf[cur];
            const int b = blockIdx.x * 8 + (wid >> 1);
            const int half = wid & 1;
            float hreg[32];
#pragma unroll
            for (int i = 0; i < 32; i++)
                hreg[i] = __ldcg(&hcur[(long)b * HID + lane + 32 * i]);
            const int o0 = half * 28, o1 = half ? INSZ : 28;
            for (int o = o0; o < o1; o++) {
                float s = 0.f;
#pragma unroll
                for (int i = 0; i < 32; i++)
                    s += hreg[i] * fcw[(long)o * HID + lane + 32 * i];
#pragma unroll
                for (int off = 16; off; off >>= 1) s += __shfl_xor_sync(0xffffffffu, s, off);
                if (lane == 0) {
                    float inp = (td == 0) ? dec[(long)b * OUT_STRIDE + o]
                                          : out[(long)b * OUT_STRIDE + (td - 1) * INSZ + o];
                    float v = inp + s + fcb[o];
                    out[(long)b * OUT_STRIDE + td * INSZ + o] = v;
                    if (td < TGT_STEPS - 1) {
                        long x = (long)(td + 1) * BATCH * KPAD + (long)b * KPAD + o;
                        g_decx_h[x] = __float2half_rn(v);
                    }
                }
            }
            if (td < TGT_STEPS - 1 && half == 1 && lane < KPAD - INSZ) {
                long x = (long)(td + 1) * BATCH * KPAD + (long)b * KPAD + INSZ + lane;
                g_decx_h[x] = __float2half_rn(0.f);
            }
            if (t != TOT_STEPS - 1) grid_bar(++nbar * NCTA);
        }
    }
}

// ---------------- prep kernels ----------------
__global__ void split_whh_kernel(const float* __restrict__ W) {
    long i = blockIdx.x * 256 + threadIdx.x;
    if (i >= (long)NGATE * HID) return;
    g_whh_h[i] = __float2half_rn(W[i]);
}
__global__ void split_wih_kernel(const float* __restrict__ W) {
    long i = blockIdx.x * 256 + threadIdx.x;
    if (i >= (long)NGATE * KPAD) return;
    int row = (int)(i >> 6), k = (int)(i & 63);
    float v = (k < INSZ) ? W[(long)row * INSZ + k] : 0.f;
    g_wih_h[i] = __float2half_rn(v);
}
__global__ void split_encx_kernel(const float* __restrict__ enc) {
    long i = blockIdx.x * 256 + threadIdx.x;
    if (i >= (long)SRC_STEPS * BATCH * KPAD) return;
    int t = (int)(i / (BATCH * KPAD));
    int r = (int)(i % (BATCH * KPAD));
    int b = r >> 6, k = r & 63;
    float v = (k < INSZ) ? enc[((long)b * 50 + t) * INSZ + k] : 0.f;
    g_encx_h[i] = __float2half_rn(v);
}
__global__ void split_decx0_kernel(const float* __restrict__ dec) {
    long i = blockIdx.x * 256 + threadIdx.x;
    if (i >= (long)BATCH * KPAD) return;
    int b = (int)(i >> 6), k = (int)(i & 63);
    float v = (k < INSZ) ? dec[(long)b * OUT_STRIDE + k] : 0.f;
    g_decx_h[i] = __float2half_rn(v);
}
__global__ void zero_state_kernel() {
    long i = blockIdx.x * 256 + threadIdx.x;
    if (i == 0) g_bar_ctr = 0;
    if (i >= (long)BATCH * HID) return;
    g_h0[i] = 0.f;
    g_h0h[i] = __float2half_rn(0.f);
}

extern "C" void kernel_launch(void* const* d_in, const int* in_sizes, int n_in,
                              void* d_out, int out_size)
{
    const float* enc = (const float*)d_in[0];
    const float* dec = (const float*)d_in[1];
    const float* Wih = (const float*)d_in[2];
    const float* Whh = (const float*)d_in[3];
    const float* bih = (const float*)d_in[4];
    const float* bhh = (const float*)d_in[5];
    const float* fcw = (const float*)d_in[6];
    const float* fcb = (const float*)d_in[7];
    float* out = (float*)d_out;

    cudaFuncSetAttribute(seq2seq_persistent,
                         cudaFuncAttributeMaxDynamicSharedMemorySize, SMEM_BYTES);

    split_whh_kernel<<<(NGATE * HID + 255) / 256, 256>>>(Whh);
    split_wih_kernel<<<(NGATE * KPAD + 255) / 256, 256>>>(Wih);
    split_encx_kernel<<<(SRC_STEPS * BATCH * KPAD + 255) / 256, 256>>>(enc);
    split_decx0_kernel<<<(BATCH * KPAD + 255) / 256, 256>>>(dec);
    zero_state_kernel<<<(BATCH * HID + 255) / 256, 256>>>();

    seq2seq_persistent<<<NCTA, 512, SMEM_BYTES>>>(dec, bih, bhh, fcw, fcb, out);
}